// round 7
// baseline (speedup 1.0000x reference)
#include <cuda_runtime.h>
#include <cuda_bf16.h>
#include <cstdint>
#include <float.h>

#define BATCH 65536
#define DIM   512
#define KC    1024
#define NCLS  100
#define GAMMA 0.99f
#define EPSV  1e-5f

#define DK (DIM * KC)      // 524288
#define KCC (KC * NCLS)    // 102400
#define NTILES (BATCH / 64)   // 1024 row-tiles of 64

// ---------------- scratch (device globals) ----------------
__device__ float                 g_wsq[KC];
__device__ float                 g_counts[KC];
__device__ __align__(16) float   g_esum[KC * DIM];     // [K][D]
__device__ float                 g_bhist[KC * NCLS];
__device__ int                   g_argmin[BATCH];
__device__ float                 g_n;
__device__ __align__(16) __nv_bfloat16 g_wbf[DIM * KC];  // bf16 W, [D][K]
__device__ float                 g_wt32[KC * DIM];     // W^T fp32 [K][D] (rescue)
__device__ int                   g_rescue_cnt;
__device__ int                   g_tile_ctr;
__device__ int                   g_r_row[BATCH];
__device__ int                   g_r_k[BATCH * 4];

// ---------------- PTX helpers (sm_100-base safe) ----------------
__device__ __forceinline__ uint32_t smem_u32(const void* p) {
    uint32_t a;
    asm("{ .reg .u64 t; cvta.to.shared.u64 t, %1; cvt.u32.u64 %0, t; }"
        : "=r"(a) : "l"(p));
    return a;
}
__device__ __forceinline__ void ldsm_x4(uint32_t* r, uint32_t addr) {
    asm volatile("ldmatrix.sync.aligned.m8n8.x4.shared.b16 {%0,%1,%2,%3}, [%4];"
                 : "=r"(r[0]), "=r"(r[1]), "=r"(r[2]), "=r"(r[3]) : "r"(addr));
}
__device__ __forceinline__ void ldsm_x4_t(uint32_t* r, uint32_t addr) {
    asm volatile("ldmatrix.sync.aligned.m8n8.x4.trans.shared.b16 {%0,%1,%2,%3}, [%4];"
                 : "=r"(r[0]), "=r"(r[1]), "=r"(r[2]), "=r"(r[3]) : "r"(addr));
}
__device__ __forceinline__ void mma16816(float* c, const uint32_t* a,
                                         uint32_t b0, uint32_t b1) {
    asm volatile("mma.sync.aligned.m16n8k16.row.col.f32.bf16.bf16.f32 "
                 "{%0,%1,%2,%3}, {%4,%5,%6,%7}, {%8,%9}, {%0,%1,%2,%3};"
                 : "+f"(c[0]), "+f"(c[1]), "+f"(c[2]), "+f"(c[3])
                 : "r"(a[0]), "r"(a[1]), "r"(a[2]), "r"(a[3]), "r"(b0), "r"(b1));
}
__device__ __forceinline__ void cp_async16(uint32_t dst, const void* src) {
    asm volatile("cp.async.cg.shared.global [%0], [%1], 16;"
                 :: "r"(dst), "l"(src) : "memory");
}
#define CP_COMMIT() asm volatile("cp.async.commit_group;" ::: "memory")
#define CP_WAIT2()  asm volatile("cp.async.wait_group 2;"  ::: "memory")
#define CP_WAIT0()  asm volatile("cp.async.wait_group 0;"  ::: "memory")
__device__ __forceinline__ uint32_t bf2u(float lo, float hi) {
    __nv_bfloat162 p = __floats2bfloat162_rn(lo, hi);
    return *reinterpret_cast<uint32_t*>(&p);
}

// ---------------------------------------------------------------
__global__ void zero_kernel() {
    int total = KC + KC * DIM + KC * NCLS;
    for (int i = blockIdx.x * blockDim.x + threadIdx.x; i < total;
         i += gridDim.x * blockDim.x) {
        if (i < KC) g_counts[i] = 0.0f;
        else if (i < KC + KC * DIM) g_esum[i - KC] = 0.0f;
        else g_bhist[i - KC - KC * DIM] = 0.0f;
    }
    if (blockIdx.x == 0 && threadIdx.x == 0) { g_rescue_cnt = 0; g_tile_ctr = 0; }
}

__global__ void wsq_kernel(const float* __restrict__ W) {
    int k = blockIdx.x * blockDim.x + threadIdx.x;
    if (k >= KC) return;
    float a = 0.0f;
    #pragma unroll 8
    for (int d = 0; d < DIM; d++) {
        float w = W[d * KC + k];
        a += w * w;
    }
    g_wsq[k] = a;
}

// Transpose W [D][K] -> W^T fp32 [K][D] (rescue) + write bf16 copy [D][K]
__global__ void wt_kernel(const float* __restrict__ W) {
    __shared__ float tile[32][33];
    int k0 = blockIdx.x * 32, d0 = blockIdx.y * 32;
    int tx = threadIdx.x, ty = threadIdx.y;   // (32, 8)
    #pragma unroll
    for (int j = 0; j < 4; j++) {
        size_t gi = (size_t)(d0 + ty + 8 * j) * KC + k0 + tx;
        float v = W[gi];
        tile[ty + 8 * j][tx] = v;
        g_wbf[gi] = __float2bfloat16_rn(v);
    }
    __syncthreads();
    #pragma unroll
    for (int j = 0; j < 4; j++)
        g_wt32[(size_t)(k0 + ty + 8 * j) * DIM + d0 + tx] = tile[tx][ty + 8 * j];
}

// ---------------------------------------------------------------
// Persistent work-stealing mma.sync GEMM + top-k argmin.
// 148 CTAs grab 64-row tiles from an atomic counter (1024 tiles).
// Per tile: A (64x512 bf16) in smem; B in a 4-stage cp.async ring,
// chunks of 64d x 256n (32KB), ONE __syncthreads per chunk.
// 8 warps (2m x 4n), warp tile 32x64.
// ---------------------------------------------------------------
#define SA_OFF   0                     // 65536: A [64][512] bf16, row 1024B
#define SB_OFF   65536                 // 4 x 32768 B ring, row 512B
#define WSQ_OFF  (SB_OFF + 131072)     // 196608, 4096 bytes
#define MSC_OFF  (WSQ_OFF + 4096)      // 16 bytes (tile broadcast)
#define RED_OFF  SB_OFF                // reuse ring for merge: 64*16*16 = 16384
#define SM_TOTAL (MSC_OFF + 16)        // 200720
#define RESCUE_T 2.0f

__device__ __forceinline__ void load_b_chunk(uint32_t smb, int c, int tid) {
    int stage = c & 3;
    int d0 = (c & 7) * 64, n0 = (c >> 3) * 256;
    #pragma unroll
    for (int t = 0; t < 8; t++) {
        int ul = t * 256 + tid;          // 0..2047 16B units
        int kr = ul >> 5, u = ul & 31;
        cp_async16(smb + SB_OFF + stage * 32768 + kr * 512 + ((u ^ (kr & 7)) * 16),
                   &g_wbf[(size_t)(d0 + kr) * KC + n0 + u * 8]);
    }
}

__global__ __launch_bounds__(256, 1)
void argmin_mma(const float* __restrict__ X, float* __restrict__ out_am) {
    extern __shared__ unsigned char sm[];
    uint32_t smb = smem_u32(sm);
    float*  s_wsq  = (float*)(sm + WSQ_OFF);
    int*    s_tile = (int*)(sm + MSC_OFF);
    float4* red    = (float4*)(sm + RED_OFF);

    int tid  = threadIdx.x;
    int lane = tid & 31;
    int wid  = tid >> 5;
    int wm   = wid >> 2;        // 0..1 -> rows wm*32..+32
    int wn   = wid & 3;         // 0..3 -> cols wn*64..+64

    #pragma unroll
    for (int i = tid; i < KC; i += 256) s_wsq[i] = g_wsq[i];

    int mx = lane & 7;
    int hi = lane >> 4;
    int kl = lane & 15;
    int kx = kl & 7;

    while (true) {
        if (tid == 0) s_tile[0] = atomicAdd(&g_tile_ctr, 1);
        __syncthreads();
        int tile = s_tile[0];
        __syncthreads();          // everyone read s_tile before reuse
        if (tile >= NTILES) break;
        int row0 = tile * 64;

        // ---- load A tile (64 x 512) -> bf16 swizzled smem ----
        #pragma unroll
        for (int it = 0; it < 16; it++) {
            int ul = it * 256 + tid;        // 4096 16B units
            int r = ul >> 6, u = ul & 63;
            const float4* xp = reinterpret_cast<const float4*>(
                &X[(size_t)(row0 + r) * DIM + u * 8]);
            float4 f0 = xp[0], f1 = xp[1];
            uint4 q;
            q.x = bf2u(f0.x, f0.y); q.y = bf2u(f0.z, f0.w);
            q.z = bf2u(f1.x, f1.y); q.w = bf2u(f1.z, f1.w);
            *reinterpret_cast<uint4*>(sm + SA_OFF + r * 1024 + ((u ^ (r & 7)) * 16)) = q;
        }

        // prologue: stages 0..2
        load_b_chunk(smb, 0, tid); CP_COMMIT();
        load_b_chunk(smb, 1, tid); CP_COMMIT();
        load_b_chunk(smb, 2, tid); CP_COMMIT();

        float tv1[4], tv2[4];
        int   tk1[4], tk2[4];
        #pragma unroll
        for (int s = 0; s < 4; s++) { tv1[s] = FLT_MAX; tv2[s] = FLT_MAX; tk1[s] = KC; tk2[s] = KC; }

        for (int nc = 0; nc < 4; nc++) {
            float acc[2][8][4];
            #pragma unroll
            for (int i = 0; i < 2; i++)
                #pragma unroll
                for (int j = 0; j < 8; j++)
                    #pragma unroll
                    for (int c = 0; c < 4; c++) acc[i][j][c] = 0.0f;

            for (int dc = 0; dc < 8; dc++) {
                int c = nc * 8 + dc;
                CP_WAIT2();               // chunk c landed (<=2 younger outstanding)
                __syncthreads();          // visible CTA-wide; stage (c+3)&3 free
                if (c + 3 < 32) load_b_chunk(smb, c + 3, tid);
                CP_COMMIT();
                uint32_t bbase = smb + SB_OFF + (c & 3) * 32768;
                #pragma unroll
                for (int ks = 0; ks < 4; ks++) {
                    uint32_t a[2][4];
                    #pragma unroll
                    for (int i = 0; i < 2; i++) {
                        int row = wm * 32 + i * 16 + kl;
                        ldsm_x4(a[i], smb + SA_OFF + row * 1024 +
                                      (((dc * 8 + ks * 2 + hi) ^ mx) * 16));
                    }
                    uint32_t bfr[4][4];
                    #pragma unroll
                    for (int jj = 0; jj < 4; jj++)
                        ldsm_x4_t(bfr[jj], bbase + (ks * 16 + kl) * 512 +
                                           (((wn * 8 + jj * 2 + hi) ^ kx) * 16));
                    #pragma unroll
                    for (int i = 0; i < 2; i++)
                        #pragma unroll
                        for (int jj = 0; jj < 4; jj++) {
                            mma16816(acc[i][jj * 2],     a[i], bfr[jj][0], bfr[jj][1]);
                            mma16816(acc[i][jj * 2 + 1], a[i], bfr[jj][2], bfr[jj][3]);
                        }
                }
            }

            // ---- epilogue: scores + running top-2 per row-slot ----
            int kbase = nc * 256 + wn * 64 + (lane & 3) * 2;
            #pragma unroll
            for (int i = 0; i < 2; i++)
                #pragma unroll
                for (int h = 0; h < 2; h++) {
                    int slot = i * 2 + h;
                    #pragma unroll
                    for (int j = 0; j < 8; j++) {
                        int kg = kbase + j * 8;
                        float s0 = fmaf(-2.0f, acc[i][j][h * 2 + 0], s_wsq[kg]);
                        float s1 = fmaf(-2.0f, acc[i][j][h * 2 + 1], s_wsq[kg + 1]);
                        if (s0 < tv1[slot])      { tv2[slot] = tv1[slot]; tk2[slot] = tk1[slot]; tv1[slot] = s0; tk1[slot] = kg; }
                        else if (s0 < tv2[slot]) { tv2[slot] = s0; tk2[slot] = kg; }
                        if (s1 < tv1[slot])      { tv2[slot] = tv1[slot]; tk2[slot] = tk1[slot]; tv1[slot] = s1; tk1[slot] = kg + 1; }
                        else if (s1 < tv2[slot]) { tv2[slot] = s1; tk2[slot] = kg + 1; }
                    }
                }
        }

        // ---- per-thread top-2 -> merge smem (ring dead until next tile) ----
        CP_WAIT0();
        __syncthreads();
        int ci = wn * 4 + (lane & 3);
        #pragma unroll
        for (int slot = 0; slot < 4; slot++) {
            int i = slot >> 1, h = slot & 1;
            int r = wm * 32 + i * 16 + h * 8 + (lane >> 2);
            float4 e;
            e.x = tv1[slot]; e.y = __int_as_float(tk1[slot]);
            e.z = tv2[slot]; e.w = __int_as_float(tk2[slot]);
            red[r * 16 + ci] = e;
        }
        __syncthreads();

        // ---- per-row merge: top-4 of 32 candidates, lexicographic (v, k) ----
        if (tid < 64) {
            float bv[4] = {FLT_MAX, FLT_MAX, FLT_MAX, FLT_MAX};
            int   bk[4] = {KC, KC, KC, KC};
            #pragma unroll
            for (int c = 0; c < 16; c++) {
                float4 e = red[tid * 16 + c];
                float cv[2] = {e.x, e.z};
                int   ck[2] = {__float_as_int(e.y), __float_as_int(e.w)};
                #pragma unroll
                for (int w = 0; w < 2; w++) {
                    float v = cv[w]; int k = ck[w];
                    if (v < bv[3] || (v == bv[3] && k < bk[3])) {
                        bv[3] = v; bk[3] = k;
                        if (bv[3] < bv[2] || (bv[3] == bv[2] && bk[3] < bk[2])) {
                            float t = bv[2]; bv[2] = bv[3]; bv[3] = t;
                            int ti = bk[2]; bk[2] = bk[3]; bk[3] = ti;
                        }
                        if (bv[2] < bv[1] || (bv[2] == bv[1] && bk[2] < bk[1])) {
                            float t = bv[1]; bv[1] = bv[2]; bv[2] = t;
                            int ti = bk[1]; bk[1] = bk[2]; bk[2] = ti;
                        }
                        if (bv[1] < bv[0] || (bv[1] == bv[0] && bk[1] < bk[0])) {
                            float t = bv[0]; bv[0] = bv[1]; bv[1] = t;
                            int ti = bk[0]; bk[0] = bk[1]; bk[1] = ti;
                        }
                    }
                }
            }
            int b = row0 + tid;
            if (bv[1] - bv[0] > RESCUE_T) {
                g_argmin[b] = bk[0];
                out_am[b] = (float)bk[0];
            } else {
                int e = atomicAdd(&g_rescue_cnt, 1);
                g_r_row[e] = b;
                #pragma unroll
                for (int w = 0; w < 4; w++) g_r_k[e * 4 + w] = bk[w];
            }
        }
        __syncthreads();   // merge reads done before next tile reuses ring
    }
}

// ---------------------------------------------------------------
// Exact fp32 rescue: top-4 candidates per flagged row, one warp each.
// ---------------------------------------------------------------
__global__ void rescue_kernel(const float* __restrict__ X,
                              float* __restrict__ out_am) {
    int lane = threadIdx.x & 31;
    int warpGlobal = (blockIdx.x * blockDim.x + threadIdx.x) >> 5;
    int nWarps = (gridDim.x * blockDim.x) >> 5;
    int cnt = g_rescue_cnt;
    for (int e = warpGlobal; e < cnt; e += nWarps) {
        int b = g_r_row[e];
        int kk[4];
        #pragma unroll
        for (int w = 0; w < 4; w++) kk[w] = g_r_k[e * 4 + w];
        const float* xr = X + (size_t)b * DIM;
        float dot[4] = {0.0f, 0.0f, 0.0f, 0.0f};
        #pragma unroll 4
        for (int d = lane; d < DIM; d += 32) {
            float x = xr[d];
            #pragma unroll
            for (int w = 0; w < 4; w++)
                if (kk[w] < KC)
                    dot[w] += x * g_wt32[(size_t)kk[w] * DIM + d];
        }
        #pragma unroll
        for (int off = 16; off > 0; off >>= 1)
            #pragma unroll
            for (int w = 0; w < 4; w++)
                dot[w] += __shfl_xor_sync(0xffffffff, dot[w], off);
        if (lane == 0) {
            float bv = FLT_MAX; int bi = KC;
            #pragma unroll
            for (int w = 0; w < 4; w++) {
                if (kk[w] >= KC) continue;
                float s = g_wsq[kk[w]] - 2.0f * dot[w];
                if (s < bv || (s == bv && kk[w] < bi)) { bv = s; bi = kk[w]; }
            }
            g_argmin[b] = bi;
            out_am[b] = (float)bi;
        }
    }
}

// ---------------------------------------------------------------
// Scatter: warp per row, vector red.global.add.v4 (coalesced)
// ---------------------------------------------------------------
__global__ void scatter_kernel(const float* __restrict__ X,
                               const int* __restrict__ keys) {
    int warp = threadIdx.x >> 5;
    int lane = threadIdx.x & 31;
    int b = blockIdx.x * 8 + warp;
    int k = g_argmin[b];
    if (lane == 0) {
        atomicAdd(&g_counts[k], 1.0f);
        atomicAdd(&g_bhist[k * NCLS + keys[b]], 1.0f);
    }
    const float* xr = X + (size_t)b * DIM;
    float* es = g_esum + (size_t)k * DIM;
    #pragma unroll
    for (int i = 0; i < 4; i++) {
        int d = (lane + i * 32) * 4;
        float4 v = *reinterpret_cast<const float4*>(xr + d);
        asm volatile("red.global.add.v4.f32 [%0], {%1, %2, %3, %4};"
                     :: "l"(es + d), "f"(v.x), "f"(v.y), "f"(v.z), "f"(v.w) : "memory");
    }
}

__global__ void fincs_kernel(const float* __restrict__ cs,
                             float* __restrict__ out_cs) {
    __shared__ float sred[KC];
    int k = threadIdx.x;
    float c = g_counts[k];
    if (c == 0.0f) c = 1.0f;
    float ncs = cs[k] * GAMMA + (1.0f - GAMMA) * c;
    out_cs[k] = ncs;
    sred[k] = ncs;
    __syncthreads();
    for (int s = KC / 2; s > 0; s >>= 1) {
        if (k < s) sred[k] += sred[k + s];
        __syncthreads();
    }
    if (k == 0) g_n = sred[0];
}

// finalize weight + embed_avg: tiled transpose of g_esum for coalescing
__global__ void finw_kernel(const float* __restrict__ ea,
                            const float* __restrict__ out_cs,
                            float* __restrict__ out_w,
                            float* __restrict__ out_ea) {
    __shared__ float tile[32][33];
    int k0 = blockIdx.x * 32, d0 = blockIdx.y * 32;
    int tx = threadIdx.x, ty = threadIdx.y;   // (32, 8)
    #pragma unroll
    for (int j = 0; j < 4; j++)
        tile[ty + 8 * j][tx] = g_esum[(size_t)(k0 + ty + 8 * j) * DIM + d0 + tx];
    __syncthreads();
    float n = g_n;
    float csn = (out_cs[k0 + tx] + EPSV) / (n + KC * EPSV) * n;
    #pragma unroll
    for (int j = 0; j < 4; j++) {
        size_t i = (size_t)(d0 + ty + 8 * j) * KC + k0 + tx;
        float e = ea[i] * GAMMA + (1.0f - GAMMA) * tile[tx][ty + 8 * j];
        out_ea[i] = e;
        out_w[i] = e / csn;
    }
}

__global__ void finh_kernel(const float* __restrict__ hist,
                            float* __restrict__ out_h) {
    int i = blockIdx.x * blockDim.x + threadIdx.x;
    if (i >= KCC) return;
    out_h[i] = hist[i] * GAMMA + (1.0f - GAMMA) * g_bhist[i];
}

// ---------------------------------------------------------------
extern "C" void kernel_launch(void* const* d_in, const int* in_sizes, int n_in,
                              void* d_out, int out_size) {
    const float* X    = (const float*)d_in[0];  // [B,D]
    const int*   keys = (const int*)  d_in[1];  // [B]
    const float* W    = (const float*)d_in[2];  // [D,K]
    const float* cs   = (const float*)d_in[3];  // [K]
    const float* ea   = (const float*)d_in[4];  // [D,K]
    const float* hist = (const float*)d_in[5];  // [K,C]

    float* out    = (float*)d_out;
    float* out_w  = out;                        // D*K
    float* out_cs = out + DK;                   // K
    float* out_ea = out + DK + KC;              // D*K
    float* out_h  = out + DK + KC + DK;         // K*C
    float* out_am = out + DK + KC + DK + KCC;   // B

    cudaFuncSetAttribute(argmin_mma, cudaFuncAttributeMaxDynamicSharedMemorySize,
                         SM_TOTAL);

    int nsm = 148;
    cudaDeviceGetAttribute(&nsm, cudaDevAttrMultiProcessorCount, 0);

    int total_zero = KC + KC * DIM + KC * NCLS;
    zero_kernel<<<(total_zero + 255) / 256, 256>>>();
    wsq_kernel<<<(KC + 255) / 256, 256>>>(W);
    wt_kernel<<<dim3(KC / 32, DIM / 32), dim3(32, 8)>>>(W);
    argmin_mma<<<nsm, 256, SM_TOTAL>>>(X, out_am);
    rescue_kernel<<<128, 128>>>(X, out_am);
    scatter_kernel<<<BATCH / 8, 256>>>(X, keys);
    fincs_kernel<<<1, KC>>>(cs, out_cs);
    finw_kernel<<<dim3(KC / 32, DIM / 32), dim3(32, 8)>>>(ea, out_cs, out_w, out_ea);
    finh_kernel<<<(KCC + 255) / 256, 256>>>(hist, out_h);
}

// round 9
// speedup vs baseline: 1.2998x; 1.2998x over previous
#include <cuda_runtime.h>
#include <cuda_bf16.h>
#include <cstdint>
#include <float.h>

#define BATCH 65536
#define DIM   512
#define KC    1024
#define NCLS  100
#define GAMMA 0.99f
#define EPSV  1e-5f

#define DK (DIM * KC)      // 524288
#define KCC (KC * NCLS)    // 102400

// ---------------- scratch (device globals) ----------------
__device__ float                 g_wsq[KC];
__device__ float                 g_counts[KC];
__device__ __align__(16) float   g_esum[KC * DIM];     // [K][D]
__device__ float                 g_bhist[KC * NCLS];
__device__ int                   g_argmin[BATCH];
__device__ float                 g_n;
__device__ __align__(16) __nv_bfloat16 g_wbf[DIM * KC];  // bf16 W, [D][K]
__device__ float                 g_wt32[KC * DIM];     // W^T fp32 [K][D] (rescue)
__device__ int                   g_rescue_cnt;
__device__ int                   g_r_row[BATCH];
__device__ int                   g_r_k[BATCH * 4];

// ---------------- PTX helpers (sm_100-base safe) ----------------
__device__ __forceinline__ uint32_t smem_u32(const void* p) {
    uint32_t a;
    asm("{ .reg .u64 t; cvta.to.shared.u64 t, %1; cvt.u32.u64 %0, t; }"
        : "=r"(a) : "l"(p));
    return a;
}
__device__ __forceinline__ void ldsm_x4(uint32_t* r, uint32_t addr) {
    asm volatile("ldmatrix.sync.aligned.m8n8.x4.shared.b16 {%0,%1,%2,%3}, [%4];"
                 : "=r"(r[0]), "=r"(r[1]), "=r"(r[2]), "=r"(r[3]) : "r"(addr));
}
__device__ __forceinline__ void ldsm_x4_t(uint32_t* r, uint32_t addr) {
    asm volatile("ldmatrix.sync.aligned.m8n8.x4.trans.shared.b16 {%0,%1,%2,%3}, [%4];"
                 : "=r"(r[0]), "=r"(r[1]), "=r"(r[2]), "=r"(r[3]) : "r"(addr));
}
__device__ __forceinline__ void mma16816(float* c, const uint32_t* a,
                                         uint32_t b0, uint32_t b1) {
    asm volatile("mma.sync.aligned.m16n8k16.row.col.f32.bf16.bf16.f32 "
                 "{%0,%1,%2,%3}, {%4,%5,%6,%7}, {%8,%9}, {%0,%1,%2,%3};"
                 : "+f"(c[0]), "+f"(c[1]), "+f"(c[2]), "+f"(c[3])
                 : "r"(a[0]), "r"(a[1]), "r"(a[2]), "r"(a[3]), "r"(b0), "r"(b1));
}
__device__ __forceinline__ void cp_async16(uint32_t dst, const void* src) {
    asm volatile("cp.async.cg.shared.global [%0], [%1], 16;"
                 :: "r"(dst), "l"(src) : "memory");
}
#define CP_COMMIT() asm volatile("cp.async.commit_group;" ::: "memory")
#define CP_WAIT1()  asm volatile("cp.async.wait_group 1;"  ::: "memory")
__device__ __forceinline__ uint32_t bf2u(float lo, float hi) {
    __nv_bfloat162 p = __floats2bfloat162_rn(lo, hi);
    return *reinterpret_cast<uint32_t*>(&p);
}
__device__ __forceinline__ void red_v4(float* addr, float4 v) {
    asm volatile("red.global.add.v4.f32 [%0], {%1, %2, %3, %4};"
                 :: "l"(addr), "f"(v.x), "f"(v.y), "f"(v.z), "f"(v.w) : "memory");
}

// ---------------------------------------------------------------
__global__ void zero_kernel() {
    int total = KC + KC + KC * DIM + KC * NCLS;   // wsq, counts, esum, bhist
    for (int i = blockIdx.x * blockDim.x + threadIdx.x; i < total;
         i += gridDim.x * blockDim.x) {
        if (i < KC) g_wsq[i] = 0.0f;
        else if (i < 2 * KC) g_counts[i - KC] = 0.0f;
        else if (i < 2 * KC + KC * DIM) g_esum[i - 2 * KC] = 0.0f;
        else g_bhist[i - 2 * KC - KC * DIM] = 0.0f;
    }
    if (blockIdx.x == 0 && threadIdx.x == 0) g_rescue_cnt = 0;
}

// Transpose W [D][K] -> W^T fp32 [K][D] + bf16 copy [D][K] + fused wsq
__global__ void wt_kernel(const float* __restrict__ W) {
    __shared__ float tile[32][33];
    __shared__ float wsqp[8][32];
    int k0 = blockIdx.x * 32, d0 = blockIdx.y * 32;
    int tx = threadIdx.x, ty = threadIdx.y;   // (32, 8)
    float sq = 0.0f;
    #pragma unroll
    for (int j = 0; j < 4; j++) {
        size_t gi = (size_t)(d0 + ty + 8 * j) * KC + k0 + tx;
        float v = W[gi];
        tile[ty + 8 * j][tx] = v;
        g_wbf[gi] = __float2bfloat16_rn(v);
        sq += v * v;
    }
    wsqp[ty][tx] = sq;
    __syncthreads();
    if (ty == 0) {
        float s = 0.0f;
        #pragma unroll
        for (int r = 0; r < 8; r++) s += wsqp[r][tx];
        atomicAdd(&g_wsq[k0 + tx], s);
    }
    #pragma unroll
    for (int j = 0; j < 4; j++)
        g_wt32[(size_t)(k0 + ty + 8 * j) * DIM + d0 + tx] = tile[tx][ty + 8 * j];
}

// ---------------------------------------------------------------
// mma.sync bf16 GEMM + top-k argmin + FUSED scatter for confident rows.
// 256 threads, 8 warps (2m x 4n), warp tile 64x64.
// CTA: 128 rows x n-chunks of 256.  A resident (128KB); B chunk
// 64d x 256n = 32KB, 2-stage cp.async ring.  (Round-6 hot loop, unchanged.)
// ---------------------------------------------------------------
#define SA_OFF   0                     // 131072: A [128][512] bf16, row 1024B
#define SB_OFF   131072                // 2 x 32768 B ring, row 512B
#define WSQ_OFF  (SB_OFF + 65536)      // 196608, 4096 bytes
#define AMK_OFF  (WSQ_OFF + 4096)      // 200704, 512 bytes (per-row argmin or -1)
#define RED_OFF  SB_OFF                // reuse ring for merge: 128*16*16 = 32768
#define SM_TOTAL (AMK_OFF + 512)       // 201216
#define RESCUE_T 2.0f

__device__ __forceinline__ void load_b_chunk(uint32_t smb, int c, int tid) {
    int stage = c & 1;
    int d0 = (c & 7) * 64, n0 = (c >> 3) * 256;
    #pragma unroll
    for (int t = 0; t < 8; t++) {
        int ul = t * 256 + tid;          // 0..2047 16B units
        int kr = ul >> 5, u = ul & 31;
        cp_async16(smb + SB_OFF + stage * 32768 + kr * 512 + ((u ^ (kr & 7)) * 16),
                   &g_wbf[(size_t)(d0 + kr) * KC + n0 + u * 8]);
    }
}

__global__ __launch_bounds__(256, 1)
void argmin_mma(const float* __restrict__ X, const int* __restrict__ keys,
                float* __restrict__ out_am) {
    extern __shared__ unsigned char sm[];
    uint32_t smb = smem_u32(sm);
    float*  s_wsq = (float*)(sm + WSQ_OFF);
    int*    s_amk = (int*)(sm + AMK_OFF);
    float4* red   = (float4*)(sm + RED_OFF);

    int tid  = threadIdx.x;
    int lane = tid & 31;
    int wid  = tid >> 5;
    int wm   = wid >> 2;        // 0..1 -> rows wm*64..+64
    int wn   = wid & 3;         // 0..3 -> cols wn*64..+64
    int row0 = blockIdx.x * 128;

    #pragma unroll
    for (int i = tid; i < KC; i += 256) s_wsq[i] = g_wsq[i];

    // ---- load X tile -> bf16 swizzled smem (A resident) ----
    #pragma unroll
    for (int it = 0; it < 32; it++) {
        int ul = it * 256 + tid;        // 8192 16B units
        int r = ul >> 6, u = ul & 63;
        const float4* xp = reinterpret_cast<const float4*>(
            &X[(size_t)(row0 + r) * DIM + u * 8]);
        float4 f0 = xp[0], f1 = xp[1];
        uint4 q;
        q.x = bf2u(f0.x, f0.y); q.y = bf2u(f0.z, f0.w);
        q.z = bf2u(f1.x, f1.y); q.w = bf2u(f1.z, f1.w);
        *reinterpret_cast<uint4*>(sm + SA_OFF + r * 1024 + ((u ^ (r & 7)) * 16)) = q;
    }

    // prologue: stage 0
    load_b_chunk(smb, 0, tid); CP_COMMIT();

    float tv1[8], tv2[8];
    int   tk1[8], tk2[8];
    #pragma unroll
    for (int s = 0; s < 8; s++) { tv1[s] = FLT_MAX; tv2[s] = FLT_MAX; tk1[s] = KC; tk2[s] = KC; }

    int mx = lane & 7;          // A row & 7
    int hi = lane >> 4;
    int kl = lane & 15;
    int kx = kl & 7;

    for (int nc = 0; nc < 4; nc++) {
        float acc[4][8][4];
        #pragma unroll
        for (int i = 0; i < 4; i++)
            #pragma unroll
            for (int j = 0; j < 8; j++)
                #pragma unroll
                for (int c = 0; c < 4; c++) acc[i][j][c] = 0.0f;

        for (int dc = 0; dc < 8; dc++) {
            int c = nc * 8 + dc;
            if (c + 1 < 32) load_b_chunk(smb, c + 1, tid);
            CP_COMMIT();
            CP_WAIT1();                   // chunk c complete
            __syncthreads();              // visible CTA-wide
            uint32_t bbase = smb + SB_OFF + (c & 1) * 32768;
            #pragma unroll
            for (int ks = 0; ks < 4; ks++) {
                uint32_t a[4][4];
                #pragma unroll
                for (int i = 0; i < 4; i++) {
                    int row = wm * 64 + i * 16 + kl;
                    ldsm_x4(a[i], smb + SA_OFF + row * 1024 +
                                  (((dc * 8 + ks * 2 + hi) ^ mx) * 16));
                }
                uint32_t bfr[4][4];
                #pragma unroll
                for (int jj = 0; jj < 4; jj++)
                    ldsm_x4_t(bfr[jj], bbase + (ks * 16 + kl) * 512 +
                                       (((wn * 8 + jj * 2 + hi) ^ kx) * 16));
                #pragma unroll
                for (int i = 0; i < 4; i++)
                    #pragma unroll
                    for (int jj = 0; jj < 4; jj++) {
                        mma16816(acc[i][jj * 2],     a[i], bfr[jj][0], bfr[jj][1]);
                        mma16816(acc[i][jj * 2 + 1], a[i], bfr[jj][2], bfr[jj][3]);
                    }
            }
            __syncthreads();              // compute done before stage reuse
        }

        // ---- epilogue: scores + running top-2 per row-slot ----
        int kbase = nc * 256 + wn * 64 + (lane & 3) * 2;
        #pragma unroll
        for (int i = 0; i < 4; i++)
            #pragma unroll
            for (int h = 0; h < 2; h++) {
                int slot = i * 2 + h;
                #pragma unroll
                for (int j = 0; j < 8; j++) {
                    int kg = kbase + j * 8;
                    float s0 = fmaf(-2.0f, acc[i][j][h * 2 + 0], s_wsq[kg]);
                    float s1 = fmaf(-2.0f, acc[i][j][h * 2 + 1], s_wsq[kg + 1]);
                    if (s0 < tv1[slot])      { tv2[slot] = tv1[slot]; tk2[slot] = tk1[slot]; tv1[slot] = s0; tk1[slot] = kg; }
                    else if (s0 < tv2[slot]) { tv2[slot] = s0; tk2[slot] = kg; }
                    if (s1 < tv1[slot])      { tv2[slot] = tv1[slot]; tk2[slot] = tk1[slot]; tv1[slot] = s1; tk1[slot] = kg + 1; }
                    else if (s1 < tv2[slot]) { tv2[slot] = s1; tk2[slot] = kg + 1; }
                }
            }
    }

    // ---- per-thread top-2 -> merge smem (ring no longer needed) ----
    __syncthreads();
    int ci = wn * 4 + (lane & 3);
    #pragma unroll
    for (int slot = 0; slot < 8; slot++) {
        int i = slot >> 1, h = slot & 1;
        int r = wm * 64 + i * 16 + h * 8 + (lane >> 2);
        float4 e;
        e.x = tv1[slot]; e.y = __int_as_float(tk1[slot]);
        e.z = tv2[slot]; e.w = __int_as_float(tk2[slot]);
        red[r * 16 + ci] = e;
    }
    __syncthreads();

    // ---- per-row merge: top-4 of 32 candidates, lexicographic (v, k) ----
    if (tid < 128) {
        float bv[4] = {FLT_MAX, FLT_MAX, FLT_MAX, FLT_MAX};
        int   bk[4] = {KC, KC, KC, KC};
        #pragma unroll
        for (int c = 0; c < 16; c++) {
            float4 e = red[tid * 16 + c];
            float cv[2] = {e.x, e.z};
            int   ck[2] = {__float_as_int(e.y), __float_as_int(e.w)};
            #pragma unroll
            for (int w = 0; w < 2; w++) {
                float v = cv[w]; int k = ck[w];
                if (v < bv[3] || (v == bv[3] && k < bk[3])) {
                    bv[3] = v; bk[3] = k;
                    if (bv[3] < bv[2] || (bv[3] == bv[2] && bk[3] < bk[2])) {
                        float t = bv[2]; bv[2] = bv[3]; bv[3] = t;
                        int ti = bk[2]; bk[2] = bk[3]; bk[3] = ti;
                    }
                    if (bv[2] < bv[1] || (bv[2] == bv[1] && bk[2] < bk[1])) {
                        float t = bv[1]; bv[1] = bv[2]; bv[2] = t;
                        int ti = bk[1]; bk[1] = bk[2]; bk[2] = ti;
                    }
                    if (bv[1] < bv[0] || (bv[1] == bv[0] && bk[1] < bk[0])) {
                        float t = bv[0]; bv[0] = bv[1]; bv[1] = t;
                        int ti = bk[0]; bk[0] = bk[1]; bk[1] = ti;
                    }
                }
            }
        }
        int b = row0 + tid;
        if (bv[1] - bv[0] > RESCUE_T) {
            g_argmin[b] = bk[0];
            out_am[b] = (float)bk[0];
            s_amk[tid] = bk[0];
        } else {
            int e = atomicAdd(&g_rescue_cnt, 1);
            g_r_row[e] = b;
            #pragma unroll
            for (int w = 0; w < 4; w++) g_r_k[e * 4 + w] = bk[w];
            s_amk[tid] = -1;   // rescued: scatter happens in rescue_kernel
        }
    }
    __syncthreads();

    // ---- FUSED scatter for confident rows (warp per row) ----
    for (int rr = wid; rr < 128; rr += 8) {
        int k = s_amk[rr];
        if (k < 0) continue;
        int b = row0 + rr;
        if (lane == 0) {
            atomicAdd(&g_counts[k], 1.0f);
            atomicAdd(&g_bhist[k * NCLS + keys[b]], 1.0f);
        }
        const float* xr = X + (size_t)b * DIM;
        float* es = g_esum + (size_t)k * DIM;
        #pragma unroll
        for (int i = 0; i < 4; i++) {
            int d = (lane + i * 32) * 4;
            red_v4(es + d, *reinterpret_cast<const float4*>(xr + d));
        }
    }
}

// ---------------------------------------------------------------
// Exact fp32 rescue + scatter for flagged rows, one warp each.
// ---------------------------------------------------------------
__global__ void rescue_kernel(const float* __restrict__ X,
                              const int* __restrict__ keys,
                              float* __restrict__ out_am) {
    int lane = threadIdx.x & 31;
    int warpGlobal = (blockIdx.x * blockDim.x + threadIdx.x) >> 5;
    int nWarps = (gridDim.x * blockDim.x) >> 5;
    int cnt = g_rescue_cnt;
    for (int e = warpGlobal; e < cnt; e += nWarps) {
        int b = g_r_row[e];
        int kk[4];
        #pragma unroll
        for (int w = 0; w < 4; w++) kk[w] = g_r_k[e * 4 + w];
        const float* xr = X + (size_t)b * DIM;
        float dot[4] = {0.0f, 0.0f, 0.0f, 0.0f};
        #pragma unroll 4
        for (int d = lane; d < DIM; d += 32) {
            float x = xr[d];
            #pragma unroll
            for (int w = 0; w < 4; w++)
                if (kk[w] < KC)
                    dot[w] += x * g_wt32[(size_t)kk[w] * DIM + d];
        }
        #pragma unroll
        for (int off = 16; off > 0; off >>= 1)
            #pragma unroll
            for (int w = 0; w < 4; w++)
                dot[w] += __shfl_xor_sync(0xffffffff, dot[w], off);
        // decide on lane 0, broadcast
        int bi = KC;
        if (lane == 0) {
            float bv = FLT_MAX;
            #pragma unroll
            for (int w = 0; w < 4; w++) {
                if (kk[w] >= KC) continue;
                float s = g_wsq[kk[w]] - 2.0f * dot[w];
                if (s < bv || (s == bv && kk[w] < bi)) { bv = s; bi = kk[w]; }
            }
            g_argmin[b] = bi;
            out_am[b] = (float)bi;
            atomicAdd(&g_counts[bi], 1.0f);
            atomicAdd(&g_bhist[bi * NCLS + keys[b]], 1.0f);
        }
        bi = __shfl_sync(0xffffffff, bi, 0);
        float* es = g_esum + (size_t)bi * DIM;
        #pragma unroll
        for (int i = 0; i < 4; i++) {
            int d = (lane + i * 32) * 4;
            red_v4(es + d, *reinterpret_cast<const float4*>(xr + d));
        }
    }
}

// ---------------------------------------------------------------
__global__ void fincs_kernel(const float* __restrict__ cs,
                             float* __restrict__ out_cs) {
    __shared__ float sred[KC];
    int k = threadIdx.x;
    float c = g_counts[k];
    if (c == 0.0f) c = 1.0f;
    float ncs = cs[k] * GAMMA + (1.0f - GAMMA) * c;
    out_cs[k] = ncs;
    sred[k] = ncs;
    __syncthreads();
    for (int s = KC / 2; s > 0; s >>= 1) {
        if (k < s) sred[k] += sred[k + s];
        __syncthreads();
    }
    if (k == 0) g_n = sred[0];
}

// finalize weight + embed_avg: tiled transpose of g_esum for coalescing
__global__ void finw_kernel(const float* __restrict__ ea,
                            const float* __restrict__ out_cs,
                            float* __restrict__ out_w,
                            float* __restrict__ out_ea) {
    __shared__ float tile[32][33];
    int k0 = blockIdx.x * 32, d0 = blockIdx.y * 32;
    int tx = threadIdx.x, ty = threadIdx.y;   // (32, 8)
    #pragma unroll
    for (int j = 0; j < 4; j++)
        tile[ty + 8 * j][tx] = g_esum[(size_t)(k0 + ty + 8 * j) * DIM + d0 + tx];
    __syncthreads();
    float n = g_n;
    float csn = (out_cs[k0 + tx] + EPSV) / (n + KC * EPSV) * n;
    #pragma unroll
    for (int j = 0; j < 4; j++) {
        size_t i = (size_t)(d0 + ty + 8 * j) * KC + k0 + tx;
        float e = ea[i] * GAMMA + (1.0f - GAMMA) * tile[tx][ty + 8 * j];
        out_ea[i] = e;
        out_w[i] = e / csn;
    }
}

__global__ void finh_kernel(const float* __restrict__ hist,
                            float* __restrict__ out_h) {
    int i = blockIdx.x * blockDim.x + threadIdx.x;
    if (i >= KCC) return;
    out_h[i] = hist[i] * GAMMA + (1.0f - GAMMA) * g_bhist[i];
}

// ---------------------------------------------------------------
extern "C" void kernel_launch(void* const* d_in, const int* in_sizes, int n_in,
                              void* d_out, int out_size) {
    const float* X    = (const float*)d_in[0];  // [B,D]
    const int*   keys = (const int*)  d_in[1];  // [B]
    const float* W    = (const float*)d_in[2];  // [D,K]
    const float* cs   = (const float*)d_in[3];  // [K]
    const float* ea   = (const float*)d_in[4];  // [D,K]
    const float* hist = (const float*)d_in[5];  // [K,C]

    float* out    = (float*)d_out;
    float* out_w  = out;                        // D*K
    float* out_cs = out + DK;                   // K
    float* out_ea = out + DK + KC;              // D*K
    float* out_h  = out + DK + KC + DK;         // K*C
    float* out_am = out + DK + KC + DK + KCC;   // B

    cudaFuncSetAttribute(argmin_mma, cudaFuncAttributeMaxDynamicSharedMemorySize,
                         SM_TOTAL);

    zero_kernel<<<148, 256>>>();
    wt_kernel<<<dim3(KC / 32, DIM / 32), dim3(32, 8)>>>(W);
    argmin_mma<<<BATCH / 128, 256, SM_TOTAL>>>(X, keys, out_am);
    rescue_kernel<<<148, 256>>>(X, keys, out_am);
    fincs_kernel<<<1, KC>>>(cs, out_cs);
    finw_kernel<<<dim3(KC / 32, DIM / 32), dim3(32, 8)>>>(ea, out_cs, out_w, out_ea);
    finh_kernel<<<(KCC + 255) / 256, 256>>>(hist, out_h);
}

// round 10
// speedup vs baseline: 1.4174x; 1.0905x over previous
#include <cuda_runtime.h>
#include <cuda_bf16.h>
#include <cstdint>
#include <float.h>

#define BATCH 65536
#define DIM   512
#define KC    1024
#define NCLS  100
#define GAMMA 0.99f
#define EPSV  1e-5f

#define DK (DIM * KC)      // 524288
#define KCC (KC * NCLS)    // 102400

// ---------------- scratch (device globals) ----------------
__device__ float                 g_wsq[KC];
__device__ float                 g_counts[KC];
__device__ __align__(16) float   g_esum[KC * DIM];     // [K][D]
__device__ float                 g_bhist[KC * NCLS];
__device__ int                   g_argmin[BATCH];
__device__ float                 g_n;
__device__ __align__(16) __nv_bfloat16 g_wbf[DIM * KC];  // bf16 W, [D][K]
__device__ float                 g_wt32[KC * DIM];     // W^T fp32 [K][D] (rescue)

// ---------------- PTX helpers (sm_100-base safe) ----------------
__device__ __forceinline__ uint32_t smem_u32(const void* p) {
    uint32_t a;
    asm("{ .reg .u64 t; cvta.to.shared.u64 t, %1; cvt.u32.u64 %0, t; }"
        : "=r"(a) : "l"(p));
    return a;
}
__device__ __forceinline__ void ldsm_x4(uint32_t* r, uint32_t addr) {
    asm volatile("ldmatrix.sync.aligned.m8n8.x4.shared.b16 {%0,%1,%2,%3}, [%4];"
                 : "=r"(r[0]), "=r"(r[1]), "=r"(r[2]), "=r"(r[3]) : "r"(addr));
}
__device__ __forceinline__ void ldsm_x4_t(uint32_t* r, uint32_t addr) {
    asm volatile("ldmatrix.sync.aligned.m8n8.x4.trans.shared.b16 {%0,%1,%2,%3}, [%4];"
                 : "=r"(r[0]), "=r"(r[1]), "=r"(r[2]), "=r"(r[3]) : "r"(addr));
}
__device__ __forceinline__ void mma16816(float* c, const uint32_t* a,
                                         uint32_t b0, uint32_t b1) {
    asm volatile("mma.sync.aligned.m16n8k16.row.col.f32.bf16.bf16.f32 "
                 "{%0,%1,%2,%3}, {%4,%5,%6,%7}, {%8,%9}, {%0,%1,%2,%3};"
                 : "+f"(c[0]), "+f"(c[1]), "+f"(c[2]), "+f"(c[3])
                 : "r"(a[0]), "r"(a[1]), "r"(a[2]), "r"(a[3]), "r"(b0), "r"(b1));
}
__device__ __forceinline__ void cp_async16(uint32_t dst, const void* src) {
    asm volatile("cp.async.cg.shared.global [%0], [%1], 16;"
                 :: "r"(dst), "l"(src) : "memory");
}
#define CP_COMMIT() asm volatile("cp.async.commit_group;" ::: "memory")
#define CP_WAIT1()  asm volatile("cp.async.wait_group 1;"  ::: "memory")
__device__ __forceinline__ uint32_t bf2u(float lo, float hi) {
    __nv_bfloat162 p = __floats2bfloat162_rn(lo, hi);
    return *reinterpret_cast<uint32_t*>(&p);
}
__device__ __forceinline__ void red_v4(float* addr, float4 v) {
    asm volatile("red.global.add.v4.f32 [%0], {%1, %2, %3, %4};"
                 :: "l"(addr), "f"(v.x), "f"(v.y), "f"(v.z), "f"(v.w) : "memory");
}

// ---------------------------------------------------------------
__global__ void zero_kernel() {
    int total = KC + KC + KC * DIM + KC * NCLS;   // wsq, counts, esum, bhist
    for (int i = blockIdx.x * blockDim.x + threadIdx.x; i < total;
         i += gridDim.x * blockDim.x) {
        if (i < KC) g_wsq[i] = 0.0f;
        else if (i < 2 * KC) g_counts[i - KC] = 0.0f;
        else if (i < 2 * KC + KC * DIM) g_esum[i - 2 * KC] = 0.0f;
        else g_bhist[i - 2 * KC - KC * DIM] = 0.0f;
    }
}

// Transpose W [D][K] -> W^T fp32 [K][D] + bf16 copy [D][K] + fused wsq
__global__ void wt_kernel(const float* __restrict__ W) {
    __shared__ float tile[32][33];
    __shared__ float wsqp[8][32];
    int k0 = blockIdx.x * 32, d0 = blockIdx.y * 32;
    int tx = threadIdx.x, ty = threadIdx.y;   // (32, 8)
    float sq = 0.0f;
    #pragma unroll
    for (int j = 0; j < 4; j++) {
        size_t gi = (size_t)(d0 + ty + 8 * j) * KC + k0 + tx;
        float v = W[gi];
        tile[ty + 8 * j][tx] = v;
        g_wbf[gi] = __float2bfloat16_rn(v);
        sq += v * v;
    }
    wsqp[ty][tx] = sq;
    __syncthreads();
    if (ty == 0) {
        float s = 0.0f;
        #pragma unroll
        for (int r = 0; r < 8; r++) s += wsqp[r][tx];
        atomicAdd(&g_wsq[k0 + tx], s);
    }
    #pragma unroll
    for (int j = 0; j < 4; j++)
        g_wt32[(size_t)(k0 + ty + 8 * j) * DIM + d0 + tx] = tile[tx][ty + 8 * j];
}

// ---------------------------------------------------------------
// mma.sync bf16 GEMM + top-k argmin + FUSED in-CTA rescue + scatter.
// 256 threads, 8 warps (2m x 4n), warp tile 64x64.
// CTA: 128 rows x n-chunks of 256.  A resident (128KB); B chunk
// 64d x 256n = 32KB, 2-stage cp.async ring.  (Round-6 hot loop, unchanged.)
// ---------------------------------------------------------------
#define SA_OFF   0                     // 131072: A [128][512] bf16, row 1024B
#define SB_OFF   131072                // 2 x 32768 B ring, row 512B
#define WSQ_OFF  (SB_OFF + 65536)      // 196608, 4096 bytes
#define AMK_OFF  (WSQ_OFF + 4096)      // 200704, 512 bytes (argmin or -1 per row)
#define CAND_OFF (AMK_OFF + 512)       // 201216, 2048 bytes (top-4 cand per row)
#define RED_OFF  SB_OFF                // reuse ring for merge: 128*16*16 = 32768
#define SM_TOTAL (CAND_OFF + 2048)     // 203264
#define RESCUE_T 2.0f

__device__ __forceinline__ void load_b_chunk(uint32_t smb, int c, int tid) {
    int stage = c & 1;
    int d0 = (c & 7) * 64, n0 = (c >> 3) * 256;
    #pragma unroll
    for (int t = 0; t < 8; t++) {
        int ul = t * 256 + tid;          // 0..2047 16B units
        int kr = ul >> 5, u = ul & 31;
        cp_async16(smb + SB_OFF + stage * 32768 + kr * 512 + ((u ^ (kr & 7)) * 16),
                   &g_wbf[(size_t)(d0 + kr) * KC + n0 + u * 8]);
    }
}

__global__ __launch_bounds__(256, 1)
void argmin_mma(const float* __restrict__ X, const int* __restrict__ keys,
                float* __restrict__ out_am) {
    extern __shared__ unsigned char sm[];
    uint32_t smb = smem_u32(sm);
    float*  s_wsq  = (float*)(sm + WSQ_OFF);
    int*    s_amk  = (int*)(sm + AMK_OFF);
    int*    s_cand = (int*)(sm + CAND_OFF);    // [128][4]
    float4* red    = (float4*)(sm + RED_OFF);

    int tid  = threadIdx.x;
    int lane = tid & 31;
    int wid  = tid >> 5;
    int wm   = wid >> 2;        // 0..1 -> rows wm*64..+64
    int wn   = wid & 3;         // 0..3 -> cols wn*64..+64
    int row0 = blockIdx.x * 128;

    #pragma unroll
    for (int i = tid; i < KC; i += 256) s_wsq[i] = g_wsq[i];

    // ---- load X tile -> bf16 swizzled smem (A resident) ----
    #pragma unroll
    for (int it = 0; it < 32; it++) {
        int ul = it * 256 + tid;        // 8192 16B units
        int r = ul >> 6, u = ul & 63;
        const float4* xp = reinterpret_cast<const float4*>(
            &X[(size_t)(row0 + r) * DIM + u * 8]);
        float4 f0 = xp[0], f1 = xp[1];
        uint4 q;
        q.x = bf2u(f0.x, f0.y); q.y = bf2u(f0.z, f0.w);
        q.z = bf2u(f1.x, f1.y); q.w = bf2u(f1.z, f1.w);
        *reinterpret_cast<uint4*>(sm + SA_OFF + r * 1024 + ((u ^ (r & 7)) * 16)) = q;
    }

    // prologue: stage 0
    load_b_chunk(smb, 0, tid); CP_COMMIT();

    float tv1[8], tv2[8];
    int   tk1[8], tk2[8];
    #pragma unroll
    for (int s = 0; s < 8; s++) { tv1[s] = FLT_MAX; tv2[s] = FLT_MAX; tk1[s] = KC; tk2[s] = KC; }

    int mx = lane & 7;          // A row & 7
    int hi = lane >> 4;
    int kl = lane & 15;
    int kx = kl & 7;

    for (int nc = 0; nc < 4; nc++) {
        float acc[4][8][4];
        #pragma unroll
        for (int i = 0; i < 4; i++)
            #pragma unroll
            for (int j = 0; j < 8; j++)
                #pragma unroll
                for (int c = 0; c < 4; c++) acc[i][j][c] = 0.0f;

        for (int dc = 0; dc < 8; dc++) {
            int c = nc * 8 + dc;
            if (c + 1 < 32) load_b_chunk(smb, c + 1, tid);
            CP_COMMIT();
            CP_WAIT1();                   // chunk c complete
            __syncthreads();              // visible CTA-wide
            uint32_t bbase = smb + SB_OFF + (c & 1) * 32768;
            #pragma unroll
            for (int ks = 0; ks < 4; ks++) {
                uint32_t a[4][4];
                #pragma unroll
                for (int i = 0; i < 4; i++) {
                    int row = wm * 64 + i * 16 + kl;
                    ldsm_x4(a[i], smb + SA_OFF + row * 1024 +
                                  (((dc * 8 + ks * 2 + hi) ^ mx) * 16));
                }
                uint32_t bfr[4][4];
                #pragma unroll
                for (int jj = 0; jj < 4; jj++)
                    ldsm_x4_t(bfr[jj], bbase + (ks * 16 + kl) * 512 +
                                       (((wn * 8 + jj * 2 + hi) ^ kx) * 16));
                #pragma unroll
                for (int i = 0; i < 4; i++)
                    #pragma unroll
                    for (int jj = 0; jj < 4; jj++) {
                        mma16816(acc[i][jj * 2],     a[i], bfr[jj][0], bfr[jj][1]);
                        mma16816(acc[i][jj * 2 + 1], a[i], bfr[jj][2], bfr[jj][3]);
                    }
            }
            __syncthreads();              // compute done before stage reuse
        }

        // ---- epilogue: scores + running top-2 per row-slot ----
        int kbase = nc * 256 + wn * 64 + (lane & 3) * 2;
        #pragma unroll
        for (int i = 0; i < 4; i++)
            #pragma unroll
            for (int h = 0; h < 2; h++) {
                int slot = i * 2 + h;
                #pragma unroll
                for (int j = 0; j < 8; j++) {
                    int kg = kbase + j * 8;
                    float s0 = fmaf(-2.0f, acc[i][j][h * 2 + 0], s_wsq[kg]);
                    float s1 = fmaf(-2.0f, acc[i][j][h * 2 + 1], s_wsq[kg + 1]);
                    if (s0 < tv1[slot])      { tv2[slot] = tv1[slot]; tk2[slot] = tk1[slot]; tv1[slot] = s0; tk1[slot] = kg; }
                    else if (s0 < tv2[slot]) { tv2[slot] = s0; tk2[slot] = kg; }
                    if (s1 < tv1[slot])      { tv2[slot] = tv1[slot]; tk2[slot] = tk1[slot]; tv1[slot] = s1; tk1[slot] = kg + 1; }
                    else if (s1 < tv2[slot]) { tv2[slot] = s1; tk2[slot] = kg + 1; }
                }
            }
    }

    // ---- per-thread top-2 -> merge smem (ring no longer needed) ----
    __syncthreads();
    int ci = wn * 4 + (lane & 3);
    #pragma unroll
    for (int slot = 0; slot < 8; slot++) {
        int i = slot >> 1, h = slot & 1;
        int r = wm * 64 + i * 16 + h * 8 + (lane >> 2);
        float4 e;
        e.x = tv1[slot]; e.y = __int_as_float(tk1[slot]);
        e.z = tv2[slot]; e.w = __int_as_float(tk2[slot]);
        red[r * 16 + ci] = e;
    }
    __syncthreads();

    // ---- per-row merge: top-4 of 32 candidates, lexicographic (v, k) ----
    if (tid < 128) {
        float bv[4] = {FLT_MAX, FLT_MAX, FLT_MAX, FLT_MAX};
        int   bk[4] = {KC, KC, KC, KC};
        #pragma unroll
        for (int c = 0; c < 16; c++) {
            float4 e = red[tid * 16 + c];
            float cv[2] = {e.x, e.z};
            int   ck[2] = {__float_as_int(e.y), __float_as_int(e.w)};
            #pragma unroll
            for (int w = 0; w < 2; w++) {
                float v = cv[w]; int k = ck[w];
                if (v < bv[3] || (v == bv[3] && k < bk[3])) {
                    bv[3] = v; bk[3] = k;
                    if (bv[3] < bv[2] || (bv[3] == bv[2] && bk[3] < bk[2])) {
                        float t = bv[2]; bv[2] = bv[3]; bv[3] = t;
                        int ti = bk[2]; bk[2] = bk[3]; bk[3] = ti;
                    }
                    if (bv[2] < bv[1] || (bv[2] == bv[1] && bk[2] < bk[1])) {
                        float t = bv[1]; bv[1] = bv[2]; bv[2] = t;
                        int ti = bk[1]; bk[1] = bk[2]; bk[2] = ti;
                    }
                    if (bv[1] < bv[0] || (bv[1] == bv[0] && bk[1] < bk[0])) {
                        float t = bv[0]; bv[0] = bv[1]; bv[1] = t;
                        int ti = bk[0]; bk[0] = bk[1]; bk[1] = ti;
                    }
                }
            }
        }
        int b = row0 + tid;
        if (bv[1] - bv[0] > RESCUE_T) {
            g_argmin[b] = bk[0];
            out_am[b] = (float)bk[0];
            s_amk[tid] = bk[0];
        } else {
            s_amk[tid] = -1;
            #pragma unroll
            for (int w = 0; w < 4; w++) s_cand[tid * 4 + w] = bk[w];
        }
    }
    __syncthreads();

    // ---- FUSED rescue + scatter (warp per row) ----
    for (int rr = wid; rr < 128; rr += 8) {
        int k = s_amk[rr];
        int b = row0 + rr;
        const float* xr = X + (size_t)b * DIM;
        if (k < 0) {
            // exact fp32 re-check of the top-4 candidates
            int kk[4];
            #pragma unroll
            for (int w = 0; w < 4; w++) kk[w] = s_cand[rr * 4 + w];
            float dot[4] = {0.0f, 0.0f, 0.0f, 0.0f};
            #pragma unroll 4
            for (int d = lane; d < DIM; d += 32) {
                float x = xr[d];
                #pragma unroll
                for (int w = 0; w < 4; w++)
                    dot[w] += x * g_wt32[(size_t)kk[w] * DIM + d];
            }
            #pragma unroll
            for (int off = 16; off > 0; off >>= 1)
                #pragma unroll
                for (int w = 0; w < 4; w++)
                    dot[w] += __shfl_xor_sync(0xffffffff, dot[w], off);
            int bi = KC;
            if (lane == 0) {
                float bvv = FLT_MAX;
                #pragma unroll
                for (int w = 0; w < 4; w++) {
                    float s = s_wsq[kk[w]] - 2.0f * dot[w];
                    if (s < bvv || (s == bvv && kk[w] < bi)) { bvv = s; bi = kk[w]; }
                }
                g_argmin[b] = bi;
                out_am[b] = (float)bi;
            }
            k = __shfl_sync(0xffffffff, bi, 0);
        }
        if (lane == 0) {
            atomicAdd(&g_counts[k], 1.0f);
            atomicAdd(&g_bhist[k * NCLS + keys[b]], 1.0f);
        }
        float* es = g_esum + (size_t)k * DIM;
        #pragma unroll
        for (int i = 0; i < 4; i++) {
            int d = (lane + i * 32) * 4;
            red_v4(es + d, *reinterpret_cast<const float4*>(xr + d));
        }
    }
}

// ---------------------------------------------------------------
__global__ void fincs_kernel(const float* __restrict__ cs,
                             float* __restrict__ out_cs) {
    __shared__ float sred[KC];
    int k = threadIdx.x;
    float c = g_counts[k];
    if (c == 0.0f) c = 1.0f;
    float ncs = cs[k] * GAMMA + (1.0f - GAMMA) * c;
    out_cs[k] = ncs;
    sred[k] = ncs;
    __syncthreads();
    for (int s = KC / 2; s > 0; s >>= 1) {
        if (k < s) sred[k] += sred[k + s];
        __syncthreads();
    }
    if (k == 0) g_n = sred[0];
}

// finalize weight + embed_avg: tiled transpose of g_esum for coalescing
__global__ void finw_kernel(const float* __restrict__ ea,
                            const float* __restrict__ out_cs,
                            float* __restrict__ out_w,
                            float* __restrict__ out_ea) {
    __shared__ float tile[32][33];
    int k0 = blockIdx.x * 32, d0 = blockIdx.y * 32;
    int tx = threadIdx.x, ty = threadIdx.y;   // (32, 8)
    #pragma unroll
    for (int j = 0; j < 4; j++)
        tile[ty + 8 * j][tx] = g_esum[(size_t)(k0 + ty + 8 * j) * DIM + d0 + tx];
    __syncthreads();
    float n = g_n;
    float csn = (out_cs[k0 + tx] + EPSV) / (n + KC * EPSV) * n;
    #pragma unroll
    for (int j = 0; j < 4; j++) {
        size_t i = (size_t)(d0 + ty + 8 * j) * KC + k0 + tx;
        float e = ea[i] * GAMMA + (1.0f - GAMMA) * tile[tx][ty + 8 * j];
        out_ea[i] = e;
        out_w[i] = e / csn;
    }
}

__global__ void finh_kernel(const float* __restrict__ hist,
                            float* __restrict__ out_h) {
    int i = blockIdx.x * blockDim.x + threadIdx.x;
    if (i >= KCC) return;
    out_h[i] = hist[i] * GAMMA + (1.0f - GAMMA) * g_bhist[i];
}

// ---------------------------------------------------------------
extern "C" void kernel_launch(void* const* d_in, const int* in_sizes, int n_in,
                              void* d_out, int out_size) {
    const float* X    = (const float*)d_in[0];  // [B,D]
    const int*   keys = (const int*)  d_in[1];  // [B]
    const float* W    = (const float*)d_in[2];  // [D,K]
    const float* cs   = (const float*)d_in[3];  // [K]
    const float* ea   = (const float*)d_in[4];  // [D,K]
    const float* hist = (const float*)d_in[5];  // [K,C]

    float* out    = (float*)d_out;
    float* out_w  = out;                        // D*K
    float* out_cs = out + DK;                   // K
    float* out_ea = out + DK + KC;              // D*K
    float* out_h  = out + DK + KC + DK;         // K*C
    float* out_am = out + DK + KC + DK + KCC;   // B

    cudaFuncSetAttribute(argmin_mma, cudaFuncAttributeMaxDynamicSharedMemorySize,
                         SM_TOTAL);

    zero_kernel<<<148, 256>>>();
    wt_kernel<<<dim3(KC / 32, DIM / 32), dim3(32, 8)>>>(W);
    argmin_mma<<<BATCH / 128, 256, SM_TOTAL>>>(X, keys, out_am);
    fincs_kernel<<<1, KC>>>(cs, out_cs);
    finw_kernel<<<dim3(KC / 32, DIM / 32), dim3(32, 8)>>>(ea, out_cs, out_w, out_ea);
    finh_kernel<<<(KCC + 255) / 256, 256>>>(hist, out_h);
}

// round 11
// speedup vs baseline: 1.4844x; 1.0473x over previous
#include <cuda_runtime.h>
#include <cuda_bf16.h>
#include <cstdint>
#include <float.h>

#define BATCH 65536
#define DIM   512
#define KC    1024
#define NCLS  100
#define GAMMA 0.99f
#define EPSV  1e-5f

#define DK (DIM * KC)      // 524288
#define KCC (KC * NCLS)    // 102400

// ---------------- scratch (device globals) ----------------
__device__ float                 g_wsq[KC];
__device__ float                 g_counts[KC];
__device__ __align__(16) float   g_esum[KC * DIM];     // [K][D]
__device__ float                 g_bhist[KC * NCLS];
__device__ int                   g_argmin[BATCH];
__device__ float                 g_n;
__device__ float                 g_wt32[KC * DIM];     // W^T fp32 [K][D] (rescue)
__device__ int                   g_wmaxb[KC];          // per-col |W| max (float bits)
__device__ float                 g_wsc[KC];            // per-col W scale
__device__ __align__(16) int8_t  g_wq8t[KC * DIM];     // int8 W^T [K][D]
__device__ __align__(16) int8_t  g_xq8[(size_t)BATCH * DIM];  // int8 X [B][D]
__device__ float                 g_xsc[BATCH];         // per-row X scale

// ---------------- PTX helpers (sm_100-base safe) ----------------
__device__ __forceinline__ uint32_t smem_u32(const void* p) {
    uint32_t a;
    asm("{ .reg .u64 t; cvta.to.shared.u64 t, %1; cvt.u32.u64 %0, t; }"
        : "=r"(a) : "l"(p));
    return a;
}
__device__ __forceinline__ void ldsm_x4(uint32_t* r, uint32_t addr) {
    asm volatile("ldmatrix.sync.aligned.m8n8.x4.shared.b16 {%0,%1,%2,%3}, [%4];"
                 : "=r"(r[0]), "=r"(r[1]), "=r"(r[2]), "=r"(r[3]) : "r"(addr));
}
__device__ __forceinline__ void mma_s8(int* c, const uint32_t* a,
                                       uint32_t b0, uint32_t b1) {
    asm volatile("mma.sync.aligned.m16n8k32.row.col.s32.s8.s8.s32 "
                 "{%0,%1,%2,%3}, {%4,%5,%6,%7}, {%8,%9}, {%0,%1,%2,%3};"
                 : "+r"(c[0]), "+r"(c[1]), "+r"(c[2]), "+r"(c[3])
                 : "r"(a[0]), "r"(a[1]), "r"(a[2]), "r"(a[3]), "r"(b0), "r"(b1));
}
__device__ __forceinline__ void cp_async16(uint32_t dst, const void* src) {
    asm volatile("cp.async.cg.shared.global [%0], [%1], 16;"
                 :: "r"(dst), "l"(src) : "memory");
}
#define CP_COMMIT() asm volatile("cp.async.commit_group;" ::: "memory")
#define CP_WAIT1()  asm volatile("cp.async.wait_group 1;"  ::: "memory")
__device__ __forceinline__ void red_v4(float* addr, float4 v) {
    asm volatile("red.global.add.v4.f32 [%0], {%1, %2, %3, %4};"
                 :: "l"(addr), "f"(v.x), "f"(v.y), "f"(v.z), "f"(v.w) : "memory");
}
__device__ __forceinline__ uint32_t pack4(float a, float b, float c, float d, float inv) {
    int b0 = __float2int_rn(a * inv) & 255;
    int b1 = __float2int_rn(b * inv) & 255;
    int b2 = __float2int_rn(c * inv) & 255;
    int b3 = __float2int_rn(d * inv) & 255;
    return (uint32_t)(b0 | (b1 << 8) | (b2 << 16) | (b3 << 24));
}

// ---------------------------------------------------------------
__global__ void zero_kernel() {
    int total = 3 * KC + KC * DIM + KC * NCLS;   // wsq, counts, wmaxb, esum, bhist
    for (int i = blockIdx.x * blockDim.x + threadIdx.x; i < total;
         i += gridDim.x * blockDim.x) {
        if (i < KC) g_wsq[i] = 0.0f;
        else if (i < 2 * KC) g_counts[i - KC] = 0.0f;
        else if (i < 3 * KC) g_wmaxb[i - 2 * KC] = 0;
        else if (i < 3 * KC + KC * DIM) g_esum[i - 3 * KC] = 0.0f;
        else g_bhist[i - 3 * KC - KC * DIM] = 0.0f;
    }
}

// Transpose W [D][K] -> W^T fp32 [K][D] + fused wsq + per-col |max|
__global__ void wt_kernel(const float* __restrict__ W) {
    __shared__ float tile[32][33];
    __shared__ float wsqp[8][32];
    __shared__ float wmxp[8][32];
    int k0 = blockIdx.x * 32, d0 = blockIdx.y * 32;
    int tx = threadIdx.x, ty = threadIdx.y;   // (32, 8) — fixed k per thread
    float sq = 0.0f, mx = 0.0f;
    #pragma unroll
    for (int j = 0; j < 4; j++) {
        size_t gi = (size_t)(d0 + ty + 8 * j) * KC + k0 + tx;
        float v = W[gi];
        tile[ty + 8 * j][tx] = v;
        sq += v * v;
        mx = fmaxf(mx, fabsf(v));
    }
    wsqp[ty][tx] = sq;
    wmxp[ty][tx] = mx;
    __syncthreads();
    if (ty == 0) {
        float s = 0.0f, m = 0.0f;
        #pragma unroll
        for (int r = 0; r < 8; r++) { s += wsqp[r][tx]; m = fmaxf(m, wmxp[r][tx]); }
        atomicAdd(&g_wsq[k0 + tx], s);
        atomicMax(&g_wmaxb[k0 + tx], __float_as_int(m));
    }
    #pragma unroll
    for (int j = 0; j < 4; j++)
        g_wt32[(size_t)(k0 + ty + 8 * j) * DIM + d0 + tx] = tile[tx][ty + 8 * j];
}

// Quantize W^T -> int8 with per-column scale
__global__ void wq_kernel() {
    int idx = blockIdx.x * 256 + threadIdx.x;   // one per 4 elements
    if (idx >= KC * DIM / 4) return;
    int k = idx >> 7;                 // DIM/4 = 128
    int d4 = (idx & 127) * 4;
    float m = __int_as_float(g_wmaxb[k]);
    float inv = 127.0f / fmaxf(m, 1e-30f);
    const float4 v = *reinterpret_cast<const float4*>(&g_wt32[(size_t)k * DIM + d4]);
    *reinterpret_cast<uint32_t*>(&g_wq8t[(size_t)k * DIM + d4]) =
        pack4(v.x, v.y, v.z, v.w, inv);
    if ((idx & 127) == 0) g_wsc[k] = m / 127.0f;
}

// Quantize X -> int8 with per-row scale (warp per row)
__global__ void xq_kernel(const float* __restrict__ X) {
    int warp = (blockIdx.x * blockDim.x + threadIdx.x) >> 5;
    int lane = threadIdx.x & 31;
    const float* xr = X + (size_t)warp * DIM;
    float4 v[4];
    float mx = 0.0f;
    #pragma unroll
    for (int i = 0; i < 4; i++) {
        v[i] = *reinterpret_cast<const float4*>(xr + (lane + i * 32) * 4);
        mx = fmaxf(mx, fmaxf(fmaxf(fabsf(v[i].x), fabsf(v[i].y)),
                             fmaxf(fabsf(v[i].z), fabsf(v[i].w))));
    }
    #pragma unroll
    for (int o = 16; o > 0; o >>= 1)
        mx = fmaxf(mx, __shfl_xor_sync(0xffffffff, mx, o));
    float inv = 127.0f / fmaxf(mx, 1e-30f);
    if (lane == 0) g_xsc[warp] = fmaxf(mx, 1e-30f) / 127.0f;
    #pragma unroll
    for (int i = 0; i < 4; i++)
        *reinterpret_cast<uint32_t*>(&g_xq8[(size_t)warp * DIM + (lane + i * 32) * 4]) =
            pack4(v[i].x, v[i].y, v[i].z, v[i].w, inv);
}

// ---------------------------------------------------------------
// int8 mma.sync GEMM (exact s32 dot) + top-k argmin + fused rescue+scatter.
// 256 threads, 8 warps (2m x 4n), warp tile 64x64, k=32 bytes per mma.
// A: 128 rows x 512 bytes int8 resident (64KB); B: [256n][128d] chunks,
// 144B padded rows, 2-stage cp.async ring.
// ---------------------------------------------------------------
#define SA_OFF   0                     // 65536: A [128][512B], swizzled
#define SB_OFF   65536                 // 2 x 36864 B ring, 144B rows
#define WSQ_OFF  (SB_OFF + 73728)      // 139264
#define SWC_OFF  (WSQ_OFF + 4096)      // 143360
#define XSC_OFF  (SWC_OFF + 4096)      // 147456
#define AMK_OFF  (XSC_OFF + 512)       // 147968
#define CAND_OFF (AMK_OFF + 512)       // 148480
#define RED_OFF  SB_OFF                // reuse ring for merge (32KB)
#define SM_TOTAL (CAND_OFF + 2048)     // 150528
#define RESCUE_T 6.0f

__device__ __forceinline__ void load_b_chunk(uint32_t smb, int c, int tid) {
    int stage = c & 1;
    int d0 = (c & 3) * 128, n0 = (c >> 2) * 256;
    #pragma unroll
    for (int t = 0; t < 8; t++) {
        int ul = t * 256 + tid;          // 2048 16B units
        int n = ul >> 3, u = ul & 7;
        cp_async16(smb + SB_OFF + stage * 36864 + n * 144 + u * 16,
                   &g_wq8t[(size_t)(n0 + n) * DIM + d0 + u * 16]);
    }
}

__global__ __launch_bounds__(256, 1)
void argmin_mma(const float* __restrict__ X, const int* __restrict__ keys,
                float* __restrict__ out_am) {
    extern __shared__ unsigned char sm[];
    uint32_t smb = smem_u32(sm);
    float*  s_wsq  = (float*)(sm + WSQ_OFF);
    float*  s_swc  = (float*)(sm + SWC_OFF);
    float*  s_xsc  = (float*)(sm + XSC_OFF);
    int*    s_amk  = (int*)(sm + AMK_OFF);
    int*    s_cand = (int*)(sm + CAND_OFF);    // [128][4]
    float4* red    = (float4*)(sm + RED_OFF);

    int tid  = threadIdx.x;
    int lane = tid & 31;
    int wid  = tid >> 5;
    int wm   = wid >> 2;        // 0..1 -> rows wm*64..+64
    int wn   = wid & 3;         // 0..3 -> cols wn*64..+64
    int row0 = blockIdx.x * 128;

    #pragma unroll
    for (int i = tid; i < KC; i += 256) { s_wsq[i] = g_wsq[i]; s_swc[i] = g_wsc[i]; }
    if (tid < 128) s_xsc[tid] = g_xsc[row0 + tid];

    // ---- A tile via cp.async (int8, swizzled) ----
    #pragma unroll
    for (int it = 0; it < 16; it++) {
        int ul = it * 256 + tid;        // 4096 16B units
        int r = ul >> 5, u = ul & 31;
        cp_async16(smb + SA_OFF + r * 512 + ((u ^ (r & 7)) * 16),
                   &g_xq8[(size_t)(row0 + r) * DIM + u * 16]);
    }
    load_b_chunk(smb, 0, tid);
    CP_COMMIT();                        // group0 = A + chunk0

    float tv1[8], tv2[8];
    int   tk1[8], tk2[8];
    #pragma unroll
    for (int s = 0; s < 8; s++) { tv1[s] = FLT_MAX; tv2[s] = FLT_MAX; tk1[s] = KC; tk2[s] = KC; }

    int kl = lane & 15;
    int hi = lane >> 4;
    int mx = lane & 7;

    for (int nc = 0; nc < 4; nc++) {
        int acc[4][8][4];
        #pragma unroll
        for (int i = 0; i < 4; i++)
            #pragma unroll
            for (int j = 0; j < 8; j++)
                #pragma unroll
                for (int c = 0; c < 4; c++) acc[i][j][c] = 0;

        for (int dc = 0; dc < 4; dc++) {
            int c = nc * 4 + dc;
            if (c + 1 < 16) load_b_chunk(smb, c + 1, tid);
            CP_COMMIT();
            CP_WAIT1();                   // chunk c (and A) complete
            __syncthreads();
            uint32_t bbase = smb + SB_OFF + (c & 1) * 36864;
            #pragma unroll
            for (int ks = 0; ks < 4; ks++) {
                uint32_t a[4][4];
                #pragma unroll
                for (int i = 0; i < 4; i++) {
                    int row = wm * 64 + i * 16 + kl;
                    int u = dc * 8 + ks * 2 + hi;   // 16B unit within 512B row
                    ldsm_x4(a[i], smb + SA_OFF + row * 512 + ((u ^ mx) * 16));
                }
                // B: non-trans ldsm from [n][k] rows; r0/r1 = b0 of n-grp0/1,
                // r2/r3 = b1 of n-grp0/1
                uint32_t bfr[4][4];
                #pragma unroll
                for (int nt = 0; nt < 4; nt++)
                    ldsm_x4(bfr[nt], bbase + (wn * 64 + nt * 16 + kl) * 144 +
                                     ks * 32 + hi * 16);
                #pragma unroll
                for (int i = 0; i < 4; i++)
                    #pragma unroll
                    for (int jj = 0; jj < 8; jj++) {
                        int g = jj >> 1, o = jj & 1;
                        mma_s8(acc[i][jj], a[i], bfr[g][0 + o], bfr[g][2 + o]);
                    }
            }
            __syncthreads();              // compute done before stage reuse
        }

        // ---- epilogue: dequant scores + running top-2 per row-slot ----
        int kbase = nc * 256 + wn * 64 + (lane & 3) * 2;
        #pragma unroll
        for (int i = 0; i < 4; i++)
            #pragma unroll
            for (int h = 0; h < 2; h++) {
                int slot = i * 2 + h;
                float sxr = s_xsc[wm * 64 + i * 16 + h * 8 + (lane >> 2)];
                float m2sx = -2.0f * sxr;
                #pragma unroll
                for (int j = 0; j < 8; j++) {
                    int kg = kbase + j * 8;
                    float s0 = fmaf((float)acc[i][j][h * 2]     * s_swc[kg],     m2sx, s_wsq[kg]);
                    float s1 = fmaf((float)acc[i][j][h * 2 + 1] * s_swc[kg + 1], m2sx, s_wsq[kg + 1]);
                    if (s0 < tv1[slot])      { tv2[slot] = tv1[slot]; tk2[slot] = tk1[slot]; tv1[slot] = s0; tk1[slot] = kg; }
                    else if (s0 < tv2[slot]) { tv2[slot] = s0; tk2[slot] = kg; }
                    if (s1 < tv1[slot])      { tv2[slot] = tv1[slot]; tk2[slot] = tk1[slot]; tv1[slot] = s1; tk1[slot] = kg + 1; }
                    else if (s1 < tv2[slot]) { tv2[slot] = s1; tk2[slot] = kg + 1; }
                }
            }
    }

    // ---- per-thread top-2 -> merge smem (ring no longer needed) ----
    __syncthreads();
    int ci = wn * 4 + (lane & 3);
    #pragma unroll
    for (int slot = 0; slot < 8; slot++) {
        int i = slot >> 1, h = slot & 1;
        int r = wm * 64 + i * 16 + h * 8 + (lane >> 2);
        float4 e;
        e.x = tv1[slot]; e.y = __int_as_float(tk1[slot]);
        e.z = tv2[slot]; e.w = __int_as_float(tk2[slot]);
        red[r * 16 + ci] = e;
    }
    __syncthreads();

    // ---- per-row merge: top-4 of 32 candidates, lexicographic (v, k) ----
    if (tid < 128) {
        float bv[4] = {FLT_MAX, FLT_MAX, FLT_MAX, FLT_MAX};
        int   bk[4] = {KC, KC, KC, KC};
        #pragma unroll
        for (int c = 0; c < 16; c++) {
            float4 e = red[tid * 16 + c];
            float cv[2] = {e.x, e.z};
            int   ck[2] = {__float_as_int(e.y), __float_as_int(e.w)};
            #pragma unroll
            for (int w = 0; w < 2; w++) {
                float v = cv[w]; int k = ck[w];
                if (v < bv[3] || (v == bv[3] && k < bk[3])) {
                    bv[3] = v; bk[3] = k;
                    if (bv[3] < bv[2] || (bv[3] == bv[2] && bk[3] < bk[2])) {
                        float t = bv[2]; bv[2] = bv[3]; bv[3] = t;
                        int ti = bk[2]; bk[2] = bk[3]; bk[3] = ti;
                    }
                    if (bv[2] < bv[1] || (bv[2] == bv[1] && bk[2] < bk[1])) {
                        float t = bv[1]; bv[1] = bv[2]; bv[2] = t;
                        int ti = bk[1]; bk[1] = bk[2]; bk[2] = ti;
                    }
                    if (bv[1] < bv[0] || (bv[1] == bv[0] && bk[1] < bk[0])) {
                        float t = bv[0]; bv[0] = bv[1]; bv[1] = t;
                        int ti = bk[0]; bk[0] = bk[1]; bk[1] = ti;
                    }
                }
            }
        }
        int b = row0 + tid;
        if (bv[1] - bv[0] > RESCUE_T) {
            g_argmin[b] = bk[0];
            out_am[b] = (float)bk[0];
            s_amk[tid] = bk[0];
        } else {
            s_amk[tid] = -1;
            #pragma unroll
            for (int w = 0; w < 4; w++) s_cand[tid * 4 + w] = bk[w];
        }
    }
    __syncthreads();

    // ---- FUSED rescue + scatter (warp per row) ----
    for (int rr = wid; rr < 128; rr += 8) {
        int k = s_amk[rr];
        int b = row0 + rr;
        const float* xr = X + (size_t)b * DIM;
        if (k < 0) {
            int kk[4];
            #pragma unroll
            for (int w = 0; w < 4; w++) kk[w] = s_cand[rr * 4 + w];
            float dot[4] = {0.0f, 0.0f, 0.0f, 0.0f};
            #pragma unroll 4
            for (int d = lane; d < DIM; d += 32) {
                float x = xr[d];
                #pragma unroll
                for (int w = 0; w < 4; w++)
                    dot[w] += x * g_wt32[(size_t)kk[w] * DIM + d];
            }
            #pragma unroll
            for (int off = 16; off > 0; off >>= 1)
                #pragma unroll
                for (int w = 0; w < 4; w++)
                    dot[w] += __shfl_xor_sync(0xffffffff, dot[w], off);
            int bi = KC;
            if (lane == 0) {
                float bvv = FLT_MAX;
                #pragma unroll
                for (int w = 0; w < 4; w++) {
                    float s = s_wsq[kk[w]] - 2.0f * dot[w];
                    if (s < bvv || (s == bvv && kk[w] < bi)) { bvv = s; bi = kk[w]; }
                }
                g_argmin[b] = bi;
                out_am[b] = (float)bi;
            }
            k = __shfl_sync(0xffffffff, bi, 0);
        }
        if (lane == 0) {
            atomicAdd(&g_counts[k], 1.0f);
            atomicAdd(&g_bhist[k * NCLS + keys[b]], 1.0f);
        }
        float* es = g_esum + (size_t)k * DIM;
        #pragma unroll
        for (int i = 0; i < 4; i++) {
            int d = (lane + i * 32) * 4;
            red_v4(es + d, *reinterpret_cast<const float4*>(xr + d));
        }
    }
}

// ---------------------------------------------------------------
__global__ void fincs_kernel(const float* __restrict__ cs,
                             float* __restrict__ out_cs) {
    __shared__ float sred[KC];
    int k = threadIdx.x;
    float c = g_counts[k];
    if (c == 0.0f) c = 1.0f;
    float ncs = cs[k] * GAMMA + (1.0f - GAMMA) * c;
    out_cs[k] = ncs;
    sred[k] = ncs;
    __syncthreads();
    for (int s = KC / 2; s > 0; s >>= 1) {
        if (k < s) sred[k] += sred[k + s];
        __syncthreads();
    }
    if (k == 0) g_n = sred[0];
}

__global__ void finw_kernel(const float* __restrict__ ea,
                            const float* __restrict__ out_cs,
                            float* __restrict__ out_w,
                            float* __restrict__ out_ea) {
    __shared__ float tile[32][33];
    int k0 = blockIdx.x * 32, d0 = blockIdx.y * 32;
    int tx = threadIdx.x, ty = threadIdx.y;   // (32, 8)
    #pragma unroll
    for (int j = 0; j < 4; j++)
        tile[ty + 8 * j][tx] = g_esum[(size_t)(k0 + ty + 8 * j) * DIM + d0 + tx];
    __syncthreads();
    float n = g_n;
    float csn = (out_cs[k0 + tx] + EPSV) / (n + KC * EPSV) * n;
    #pragma unroll
    for (int j = 0; j < 4; j++) {
        size_t i = (size_t)(d0 + ty + 8 * j) * KC + k0 + tx;
        float e = ea[i] * GAMMA + (1.0f - GAMMA) * tile[tx][ty + 8 * j];
        out_ea[i] = e;
        out_w[i] = e / csn;
    }
}

__global__ void finh_kernel(const float* __restrict__ hist,
                            float* __restrict__ out_h) {
    int i = blockIdx.x * blockDim.x + threadIdx.x;
    if (i >= KCC) return;
    out_h[i] = hist[i] * GAMMA + (1.0f - GAMMA) * g_bhist[i];
}

// ---------------------------------------------------------------
extern "C" void kernel_launch(void* const* d_in, const int* in_sizes, int n_in,
                              void* d_out, int out_size) {
    const float* X    = (const float*)d_in[0];  // [B,D]
    const int*   keys = (const int*)  d_in[1];  // [B]
    const float* W    = (const float*)d_in[2];  // [D,K]
    const float* cs   = (const float*)d_in[3];  // [K]
    const float* ea   = (const float*)d_in[4];  // [D,K]
    const float* hist = (const float*)d_in[5];  // [K,C]

    float* out    = (float*)d_out;
    float* out_w  = out;                        // D*K
    float* out_cs = out + DK;                   // K
    float* out_ea = out + DK + KC;              // D*K
    float* out_h  = out + DK + KC + DK;         // K*C
    float* out_am = out + DK + KC + DK + KCC;   // B

    cudaFuncSetAttribute(argmin_mma, cudaFuncAttributeMaxDynamicSharedMemorySize,
                         SM_TOTAL);

    zero_kernel<<<148, 256>>>();
    wt_kernel<<<dim3(KC / 32, DIM / 32), dim3(32, 8)>>>(W);
    wq_kernel<<<(KC * DIM / 4 + 255) / 256, 256>>>();
    xq_kernel<<<BATCH / 8, 256>>>(X);
    argmin_mma<<<BATCH / 128, 256, SM_TOTAL>>>(X, keys, out_am);
    fincs_kernel<<<1, KC>>>(cs, out_cs);
    finw_kernel<<<dim3(KC / 32, DIM / 32), dim3(32, 8)>>>(ea, out_cs, out_w, out_ea);
    finh_kernel<<<(KCC + 255) / 256, 256>>>(hist, out_h);
}

// round 12
// speedup vs baseline: 1.5136x; 1.0197x over previous
#include <cuda_runtime.h>
#include <cuda_bf16.h>
#include <cstdint>
#include <float.h>

#define BATCH 65536
#define DIM   512
#define KC    1024
#define NCLS  100
#define GAMMA 0.99f
#define EPSV  1e-5f

#define DK (DIM * KC)      // 524288
#define KCC (KC * NCLS)    // 102400

// ---------------- scratch (device globals) ----------------
__device__ float                 g_wsq[KC];
__device__ float                 g_counts[KC];
__device__ __align__(16) float   g_esum[KC * DIM];     // [K][D]
__device__ float                 g_bhist[KC * NCLS];
__device__ int                   g_argmin[BATCH];
__device__ float                 g_n;
__device__ float                 g_wt32[KC * DIM];     // W^T fp32 [K][D] (rescue)
__device__ int                   g_wmaxb[KC];          // per-col |W| max (float bits)
__device__ float                 g_wsc[KC];            // per-col W scale
__device__ __align__(16) int8_t  g_wq8t[KC * DIM];     // int8 W^T [K][D]

// ---------------- PTX helpers (sm_100-base safe) ----------------
__device__ __forceinline__ uint32_t smem_u32(const void* p) {
    uint32_t a;
    asm("{ .reg .u64 t; cvta.to.shared.u64 t, %1; cvt.u32.u64 %0, t; }"
        : "=r"(a) : "l"(p));
    return a;
}
__device__ __forceinline__ void ldsm_x4(uint32_t* r, uint32_t addr) {
    asm volatile("ldmatrix.sync.aligned.m8n8.x4.shared.b16 {%0,%1,%2,%3}, [%4];"
                 : "=r"(r[0]), "=r"(r[1]), "=r"(r[2]), "=r"(r[3]) : "r"(addr));
}
__device__ __forceinline__ void mma_s8(int* c, const uint32_t* a,
                                       uint32_t b0, uint32_t b1) {
    asm volatile("mma.sync.aligned.m16n8k32.row.col.s32.s8.s8.s32 "
                 "{%0,%1,%2,%3}, {%4,%5,%6,%7}, {%8,%9}, {%0,%1,%2,%3};"
                 : "+r"(c[0]), "+r"(c[1]), "+r"(c[2]), "+r"(c[3])
                 : "r"(a[0]), "r"(a[1]), "r"(a[2]), "r"(a[3]), "r"(b0), "r"(b1));
}
__device__ __forceinline__ void cp_async16(uint32_t dst, const void* src) {
    asm volatile("cp.async.cg.shared.global [%0], [%1], 16;"
                 :: "r"(dst), "l"(src) : "memory");
}
#define CP_COMMIT() asm volatile("cp.async.commit_group;" ::: "memory")
#define CP_WAIT1()  asm volatile("cp.async.wait_group 1;"  ::: "memory")
__device__ __forceinline__ void red_v4(float* addr, float4 v) {
    asm volatile("red.global.add.v4.f32 [%0], {%1, %2, %3, %4};"
                 :: "l"(addr), "f"(v.x), "f"(v.y), "f"(v.z), "f"(v.w) : "memory");
}
__device__ __forceinline__ uint32_t pack4(float a, float b, float c, float d, float inv) {
    int b0 = __float2int_rn(a * inv) & 255;
    int b1 = __float2int_rn(b * inv) & 255;
    int b2 = __float2int_rn(c * inv) & 255;
    int b3 = __float2int_rn(d * inv) & 255;
    return (uint32_t)(b0 | (b1 << 8) | (b2 << 16) | (b3 << 24));
}

// ---------------------------------------------------------------
__global__ void zero_kernel() {
    int total = 3 * KC + KC * DIM + KC * NCLS;   // wsq, counts, wmaxb, esum, bhist
    for (int i = blockIdx.x * blockDim.x + threadIdx.x; i < total;
         i += gridDim.x * blockDim.x) {
        if (i < KC) g_wsq[i] = 0.0f;
        else if (i < 2 * KC) g_counts[i - KC] = 0.0f;
        else if (i < 3 * KC) g_wmaxb[i - 2 * KC] = 0;
        else if (i < 3 * KC + KC * DIM) g_esum[i - 3 * KC] = 0.0f;
        else g_bhist[i - 3 * KC - KC * DIM] = 0.0f;
    }
}

// Transpose W [D][K] -> W^T fp32 [K][D] + fused wsq + per-col |max|
__global__ void wt_kernel(const float* __restrict__ W) {
    __shared__ float tile[32][33];
    __shared__ float wsqp[8][32];
    __shared__ float wmxp[8][32];
    int k0 = blockIdx.x * 32, d0 = blockIdx.y * 32;
    int tx = threadIdx.x, ty = threadIdx.y;   // (32, 8) — fixed k per thread
    float sq = 0.0f, mx = 0.0f;
    #pragma unroll
    for (int j = 0; j < 4; j++) {
        size_t gi = (size_t)(d0 + ty + 8 * j) * KC + k0 + tx;
        float v = W[gi];
        tile[ty + 8 * j][tx] = v;
        sq += v * v;
        mx = fmaxf(mx, fabsf(v));
    }
    wsqp[ty][tx] = sq;
    wmxp[ty][tx] = mx;
    __syncthreads();
    if (ty == 0) {
        float s = 0.0f, m = 0.0f;
        #pragma unroll
        for (int r = 0; r < 8; r++) { s += wsqp[r][tx]; m = fmaxf(m, wmxp[r][tx]); }
        atomicAdd(&g_wsq[k0 + tx], s);
        atomicMax(&g_wmaxb[k0 + tx], __float_as_int(m));
    }
    #pragma unroll
    for (int j = 0; j < 4; j++)
        g_wt32[(size_t)(k0 + ty + 8 * j) * DIM + d0 + tx] = tile[tx][ty + 8 * j];
}

// Quantize W^T -> int8 with per-column scale
__global__ void wq_kernel() {
    int idx = blockIdx.x * 256 + threadIdx.x;   // one per 4 elements
    if (idx >= KC * DIM / 4) return;
    int k = idx >> 7;                 // DIM/4 = 128
    int d4 = (idx & 127) * 4;
    float m = __int_as_float(g_wmaxb[k]);
    float inv = 127.0f / fmaxf(m, 1e-30f);
    const float4 v = *reinterpret_cast<const float4*>(&g_wt32[(size_t)k * DIM + d4]);
    *reinterpret_cast<uint32_t*>(&g_wq8t[(size_t)k * DIM + d4]) =
        pack4(v.x, v.y, v.z, v.w, inv);
    if ((idx & 127) == 0) g_wsc[k] = m / 127.0f;
}

// ---------------------------------------------------------------
// int8 mma.sync GEMM (exact s32 dot) + FUSED in-CTA X quantization,
// top-k argmin, rescue, scatter.
// 256 threads, 8 warps (2m x 4n), warp tile 64x64, k=32 bytes per mma.
// A: 128 rows x 512 bytes int8, quantized in-kernel from fp32 X;
// B: [256n][128d] chunks, 144B padded rows, 2-stage cp.async ring.
// ---------------------------------------------------------------
#define SA_OFF   0                     // 65536: A [128][512B], swizzled
#define SB_OFF   65536                 // 2 x 36864 B ring, 144B rows
#define WSQ_OFF  (SB_OFF + 73728)      // 139264
#define SWC_OFF  (WSQ_OFF + 4096)      // 143360
#define XSC_OFF  (SWC_OFF + 4096)      // 147456
#define AMK_OFF  (XSC_OFF + 512)       // 147968
#define CAND_OFF (AMK_OFF + 512)       // 148480
#define RED_OFF  SB_OFF                // reuse ring for merge (32KB)
#define SM_TOTAL (CAND_OFF + 2048)     // 150528
#define RESCUE_T 6.0f

__device__ __forceinline__ void load_b_chunk(uint32_t smb, int c, int tid) {
    int stage = c & 1;
    int d0 = (c & 3) * 128, n0 = (c >> 2) * 256;
    #pragma unroll
    for (int t = 0; t < 8; t++) {
        int ul = t * 256 + tid;          // 2048 16B units
        int n = ul >> 3, u = ul & 7;
        cp_async16(smb + SB_OFF + stage * 36864 + n * 144 + u * 16,
                   &g_wq8t[(size_t)(n0 + n) * DIM + d0 + u * 16]);
    }
}

__global__ __launch_bounds__(256, 1)
void argmin_mma(const float* __restrict__ X, const int* __restrict__ keys,
                float* __restrict__ out_am) {
    extern __shared__ unsigned char sm[];
    uint32_t smb = smem_u32(sm);
    float*  s_wsq  = (float*)(sm + WSQ_OFF);
    float*  s_swc  = (float*)(sm + SWC_OFF);
    float*  s_xsc  = (float*)(sm + XSC_OFF);
    int*    s_amk  = (int*)(sm + AMK_OFF);
    int*    s_cand = (int*)(sm + CAND_OFF);    // [128][4]
    float4* red    = (float4*)(sm + RED_OFF);

    int tid  = threadIdx.x;
    int lane = tid & 31;
    int wid  = tid >> 5;
    int wm   = wid >> 2;        // 0..1 -> rows wm*64..+64
    int wn   = wid & 3;         // 0..3 -> cols wn*64..+64
    int row0 = blockIdx.x * 128;

    // start B pipeline first so quant overlaps the loads
    load_b_chunk(smb, 0, tid);
    CP_COMMIT();

    #pragma unroll
    for (int i = tid; i < KC; i += 256) { s_wsq[i] = g_wsq[i]; s_swc[i] = g_wsc[i]; }

    // ---- FUSED X quantization: warp per row, 16 rows per warp ----
    #pragma unroll
    for (int i = 0; i < 16; i++) {
        int r = wid * 16 + i;
        const float4* xp = reinterpret_cast<const float4*>(
            &X[(size_t)(row0 + r) * DIM + lane * 16]);
        float4 v0 = xp[0], v1 = xp[1], v2 = xp[2], v3 = xp[3];
        float mx8 = fmaxf(fmaxf(fmaxf(fabsf(v0.x), fabsf(v0.y)),
                                fmaxf(fabsf(v0.z), fabsf(v0.w))),
                          fmaxf(fmaxf(fabsf(v1.x), fabsf(v1.y)),
                                fmaxf(fabsf(v1.z), fabsf(v1.w))));
        mx8 = fmaxf(mx8, fmaxf(fmaxf(fabsf(v2.x), fabsf(v2.y)),
                               fmaxf(fabsf(v2.z), fabsf(v2.w))));
        mx8 = fmaxf(mx8, fmaxf(fmaxf(fabsf(v3.x), fabsf(v3.y)),
                               fmaxf(fabsf(v3.z), fabsf(v3.w))));
        #pragma unroll
        for (int o = 16; o > 0; o >>= 1)
            mx8 = fmaxf(mx8, __shfl_xor_sync(0xffffffff, mx8, o));
        float m = fmaxf(mx8, 1e-30f);
        float inv = 127.0f / m;
        uint4 q;
        q.x = pack4(v0.x, v0.y, v0.z, v0.w, inv);
        q.y = pack4(v1.x, v1.y, v1.z, v1.w, inv);
        q.z = pack4(v2.x, v2.y, v2.z, v2.w, inv);
        q.w = pack4(v3.x, v3.y, v3.z, v3.w, inv);
        *reinterpret_cast<uint4*>(sm + SA_OFF + r * 512 + ((lane ^ (r & 7)) * 16)) = q;
        if (lane == 0) s_xsc[r] = m / 127.0f;
    }

    float tv1[8], tv2[8];
    int   tk1[8], tk2[8];
    #pragma unroll
    for (int s = 0; s < 8; s++) { tv1[s] = FLT_MAX; tv2[s] = FLT_MAX; tk1[s] = KC; tk2[s] = KC; }

    int kl = lane & 15;
    int hi = lane >> 4;
    int mx = lane & 7;

    for (int nc = 0; nc < 4; nc++) {
        int acc[4][8][4];
        #pragma unroll
        for (int i = 0; i < 4; i++)
            #pragma unroll
            for (int j = 0; j < 8; j++)
                #pragma unroll
                for (int c = 0; c < 4; c++) acc[i][j][c] = 0;

        for (int dc = 0; dc < 4; dc++) {
            int c = nc * 4 + dc;
            if (c + 1 < 16) load_b_chunk(smb, c + 1, tid);
            CP_COMMIT();
            CP_WAIT1();                   // chunk c complete
            __syncthreads();              // B visible + A quant visible (1st iter)
            uint32_t bbase = smb + SB_OFF + (c & 1) * 36864;
            #pragma unroll
            for (int ks = 0; ks < 4; ks++) {
                uint32_t a[4][4];
                #pragma unroll
                for (int i = 0; i < 4; i++) {
                    int row = wm * 64 + i * 16 + kl;
                    int u = dc * 8 + ks * 2 + hi;   // 16B unit within 512B row
                    ldsm_x4(a[i], smb + SA_OFF + row * 512 + ((u ^ mx) * 16));
                }
                uint32_t bfr[4][4];
                #pragma unroll
                for (int nt = 0; nt < 4; nt++)
                    ldsm_x4(bfr[nt], bbase + (wn * 64 + nt * 16 + kl) * 144 +
                                     ks * 32 + hi * 16);
                #pragma unroll
                for (int i = 0; i < 4; i++)
                    #pragma unroll
                    for (int jj = 0; jj < 8; jj++) {
                        int g = jj >> 1, o = jj & 1;
                        mma_s8(acc[i][jj], a[i], bfr[g][0 + o], bfr[g][2 + o]);
                    }
            }
            __syncthreads();              // compute done before stage reuse
        }

        // ---- epilogue: dequant scores + running top-2 per row-slot ----
        int kbase = nc * 256 + wn * 64 + (lane & 3) * 2;
        #pragma unroll
        for (int i = 0; i < 4; i++)
            #pragma unroll
            for (int h = 0; h < 2; h++) {
                int slot = i * 2 + h;
                float sxr = s_xsc[wm * 64 + i * 16 + h * 8 + (lane >> 2)];
                float m2sx = -2.0f * sxr;
                #pragma unroll
                for (int j = 0; j < 8; j++) {
                    int kg = kbase + j * 8;
                    float s0 = fmaf((float)acc[i][j][h * 2]     * s_swc[kg],     m2sx, s_wsq[kg]);
                    float s1 = fmaf((float)acc[i][j][h * 2 + 1] * s_swc[kg + 1], m2sx, s_wsq[kg + 1]);
                    if (s0 < tv1[slot])      { tv2[slot] = tv1[slot]; tk2[slot] = tk1[slot]; tv1[slot] = s0; tk1[slot] = kg; }
                    else if (s0 < tv2[slot]) { tv2[slot] = s0; tk2[slot] = kg; }
                    if (s1 < tv1[slot])      { tv2[slot] = tv1[slot]; tk2[slot] = tk1[slot]; tv1[slot] = s1; tk1[slot] = kg + 1; }
                    else if (s1 < tv2[slot]) { tv2[slot] = s1; tk2[slot] = kg + 1; }
                }
            }
    }

    // ---- per-thread top-2 -> merge smem (ring no longer needed) ----
    __syncthreads();
    int ci = wn * 4 + (lane & 3);
    #pragma unroll
    for (int slot = 0; slot < 8; slot++) {
        int i = slot >> 1, h = slot & 1;
        int r = wm * 64 + i * 16 + h * 8 + (lane >> 2);
        float4 e;
        e.x = tv1[slot]; e.y = __int_as_float(tk1[slot]);
        e.z = tv2[slot]; e.w = __int_as_float(tk2[slot]);
        red[r * 16 + ci] = e;
    }
    __syncthreads();

    // ---- per-row merge: top-4 of 32 candidates, lexicographic (v, k) ----
    if (tid < 128) {
        float bv[4] = {FLT_MAX, FLT_MAX, FLT_MAX, FLT_MAX};
        int   bk[4] = {KC, KC, KC, KC};
        #pragma unroll
        for (int c = 0; c < 16; c++) {
            float4 e = red[tid * 16 + c];
            float cv[2] = {e.x, e.z};
            int   ck[2] = {__float_as_int(e.y), __float_as_int(e.w)};
            #pragma unroll
            for (int w = 0; w < 2; w++) {
                float v = cv[w]; int k = ck[w];
                if (v < bv[3] || (v == bv[3] && k < bk[3])) {
                    bv[3] = v; bk[3] = k;
                    if (bv[3] < bv[2] || (bv[3] == bv[2] && bk[3] < bk[2])) {
                        float t = bv[2]; bv[2] = bv[3]; bv[3] = t;
                        int ti = bk[2]; bk[2] = bk[3]; bk[3] = ti;
                    }
                    if (bv[2] < bv[1] || (bv[2] == bv[1] && bk[2] < bk[1])) {
                        float t = bv[1]; bv[1] = bv[2]; bv[2] = t;
                        int ti = bk[1]; bk[1] = bk[2]; bk[2] = ti;
                    }
                    if (bv[1] < bv[0] || (bv[1] == bv[0] && bk[1] < bk[0])) {
                        float t = bv[0]; bv[0] = bv[1]; bv[1] = t;
                        int ti = bk[0]; bk[0] = bk[1]; bk[1] = ti;
                    }
                }
            }
        }
        int b = row0 + tid;
        if (bv[1] - bv[0] > RESCUE_T) {
            g_argmin[b] = bk[0];
            out_am[b] = (float)bk[0];
            s_amk[tid] = bk[0];
        } else {
            s_amk[tid] = -1;
            #pragma unroll
            for (int w = 0; w < 4; w++) s_cand[tid * 4 + w] = bk[w];
        }
    }
    __syncthreads();

    // ---- FUSED rescue + scatter (warp per row) ----
    for (int rr = wid; rr < 128; rr += 8) {
        int k = s_amk[rr];
        int b = row0 + rr;
        const float* xr = X + (size_t)b * DIM;
        if (k < 0) {
            int kk[4];
            #pragma unroll
            for (int w = 0; w < 4; w++) kk[w] = s_cand[rr * 4 + w];
            float dot[4] = {0.0f, 0.0f, 0.0f, 0.0f};
            #pragma unroll 4
            for (int d = lane; d < DIM; d += 32) {
                float x = xr[d];
                #pragma unroll
                for (int w = 0; w < 4; w++)
                    dot[w] += x * g_wt32[(size_t)kk[w] * DIM + d];
            }
            #pragma unroll
            for (int off = 16; off > 0; off >>= 1)
                #pragma unroll
                for (int w = 0; w < 4; w++)
                    dot[w] += __shfl_xor_sync(0xffffffff, dot[w], off);
            int bi = KC;
            if (lane == 0) {
                float bvv = FLT_MAX;
                #pragma unroll
                for (int w = 0; w < 4; w++) {
                    float s = s_wsq[kk[w]] - 2.0f * dot[w];
                    if (s < bvv || (s == bvv && kk[w] < bi)) { bvv = s; bi = kk[w]; }
                }
                g_argmin[b] = bi;
                out_am[b] = (float)bi;
            }
            k = __shfl_sync(0xffffffff, bi, 0);
        }
        if (lane == 0) {
            atomicAdd(&g_counts[k], 1.0f);
            atomicAdd(&g_bhist[k * NCLS + keys[b]], 1.0f);
        }
        float* es = g_esum + (size_t)k * DIM;
        #pragma unroll
        for (int i = 0; i < 4; i++) {
            int d = (lane + i * 32) * 4;
            red_v4(es + d, *reinterpret_cast<const float4*>(xr + d));
        }
    }
}

// ---------------------------------------------------------------
__global__ void fincs_kernel(const float* __restrict__ cs,
                             float* __restrict__ out_cs) {
    __shared__ float sred[KC];
    int k = threadIdx.x;
    float c = g_counts[k];
    if (c == 0.0f) c = 1.0f;
    float ncs = cs[k] * GAMMA + (1.0f - GAMMA) * c;
    out_cs[k] = ncs;
    sred[k] = ncs;
    __syncthreads();
    for (int s = KC / 2; s > 0; s >>= 1) {
        if (k < s) sred[k] += sred[k + s];
        __syncthreads();
    }
    if (k == 0) g_n = sred[0];
}

__global__ void finw_kernel(const float* __restrict__ ea,
                            const float* __restrict__ out_cs,
                            float* __restrict__ out_w,
                            float* __restrict__ out_ea) {
    __shared__ float tile[32][33];
    int k0 = blockIdx.x * 32, d0 = blockIdx.y * 32;
    int tx = threadIdx.x, ty = threadIdx.y;   // (32, 8)
    #pragma unroll
    for (int j = 0; j < 4; j++)
        tile[ty + 8 * j][tx] = g_esum[(size_t)(k0 + ty + 8 * j) * DIM + d0 + tx];
    __syncthreads();
    float n = g_n;
    float csn = (out_cs[k0 + tx] + EPSV) / (n + KC * EPSV) * n;
    #pragma unroll
    for (int j = 0; j < 4; j++) {
        size_t i = (size_t)(d0 + ty + 8 * j) * KC + k0 + tx;
        float e = ea[i] * GAMMA + (1.0f - GAMMA) * tile[tx][ty + 8 * j];
        out_ea[i] = e;
        out_w[i] = e / csn;
    }
}

__global__ void finh_kernel(const float* __restrict__ hist,
                            float* __restrict__ out_h) {
    int i = blockIdx.x * blockDim.x + threadIdx.x;
    if (i >= KCC) return;
    out_h[i] = hist[i] * GAMMA + (1.0f - GAMMA) * g_bhist[i];
}

// ---------------------------------------------------------------
extern "C" void kernel_launch(void* const* d_in, const int* in_sizes, int n_in,
                              void* d_out, int out_size) {
    const float* X    = (const float*)d_in[0];  // [B,D]
    const int*   keys = (const int*)  d_in[1];  // [B]
    const float* W    = (const float*)d_in[2];  // [D,K]
    const float* cs   = (const float*)d_in[3];  // [K]
    const float* ea   = (const float*)d_in[4];  // [D,K]
    const float* hist = (const float*)d_in[5];  // [K,C]

    float* out    = (float*)d_out;
    float* out_w  = out;                        // D*K
    float* out_cs = out + DK;                   // K
    float* out_ea = out + DK + KC;              // D*K
    float* out_h  = out + DK + KC + DK;         // K*C
    float* out_am = out + DK + KC + DK + KCC;   // B

    cudaFuncSetAttribute(argmin_mma, cudaFuncAttributeMaxDynamicSharedMemorySize,
                         SM_TOTAL);

    zero_kernel<<<148, 256>>>();
    wt_kernel<<<dim3(KC / 32, DIM / 32), dim3(32, 8)>>>(W);
    wq_kernel<<<(KC * DIM / 4 + 255) / 256, 256>>>();
    argmin_mma<<<BATCH / 128, 256, SM_TOTAL>>>(X, keys, out_am);
    fincs_kernel<<<1, KC>>>(cs, out_cs);
    finw_kernel<<<dim3(KC / 32, DIM / 32), dim3(32, 8)>>>(ea, out_cs, out_w, out_ea);
    finh_kernel<<<(KCC + 255) / 256, 256>>>(hist, out_h);
}

// round 14
// speedup vs baseline: 2.1666x; 1.4314x over previous
#include <cuda_runtime.h>
#include <cuda_bf16.h>
#include <cstdint>
#include <float.h>

#define BATCH 65536
#define DIM   512
#define KC    1024
#define NCLS  100
#define GAMMA 0.99f
#define EPSV  1e-5f

#define DK (DIM * KC)      // 524288
#define KCC (KC * NCLS)    // 102400

// ---------------- scratch (device globals) ----------------
__device__ float                 g_wsq[KC];
__device__ float                 g_counts[KC];
__device__ __align__(16) float   g_esum[KC * DIM];     // [K][D]
__device__ float                 g_bhist[KC * NCLS];
__device__ int                   g_argmin[BATCH];
__device__ float                 g_n;
__device__ float                 g_wt32[KC * DIM];     // W^T fp32 [K][D] (rescue)
__device__ int                   g_wmaxb[KC];          // per-col |W| max (float bits)
__device__ float                 g_wsc[KC];            // per-col W scale
__device__ __align__(16) int8_t  g_wq8t[KC * DIM];     // int8 W^T [K][D]

// ---------------- PTX helpers (sm_100-base safe) ----------------
__device__ __forceinline__ uint32_t smem_u32(const void* p) {
    uint32_t a;
    asm("{ .reg .u64 t; cvta.to.shared.u64 t, %1; cvt.u32.u64 %0, t; }"
        : "=r"(a) : "l"(p));
    return a;
}
__device__ __forceinline__ void ldsm_x4(uint32_t* r, uint32_t addr) {
    asm volatile("ldmatrix.sync.aligned.m8n8.x4.shared.b16 {%0,%1,%2,%3}, [%4];"
                 : "=r"(r[0]), "=r"(r[1]), "=r"(r[2]), "=r"(r[3]) : "r"(addr));
}
__device__ __forceinline__ void mma_s8(int* c, const uint32_t* a,
                                       uint32_t b0, uint32_t b1) {
    asm volatile("mma.sync.aligned.m16n8k32.row.col.s32.s8.s8.s32 "
                 "{%0,%1,%2,%3}, {%4,%5,%6,%7}, {%8,%9}, {%0,%1,%2,%3};"
                 : "+r"(c[0]), "+r"(c[1]), "+r"(c[2]), "+r"(c[3])
                 : "r"(a[0]), "r"(a[1]), "r"(a[2]), "r"(a[3]), "r"(b0), "r"(b1));
}
__device__ __forceinline__ void cp_async16(uint32_t dst, const void* src) {
    asm volatile("cp.async.cg.shared.global [%0], [%1], 16;"
                 :: "r"(dst), "l"(src) : "memory");
}
#define CP_COMMIT() asm volatile("cp.async.commit_group;" ::: "memory")
#define CP_WAIT1()  asm volatile("cp.async.wait_group 1;"  ::: "memory")
__device__ __forceinline__ void red_v4(float* addr, float4 v) {
    asm volatile("red.global.add.v4.f32 [%0], {%1, %2, %3, %4};"
                 :: "l"(addr), "f"(v.x), "f"(v.y), "f"(v.z), "f"(v.w) : "memory");
}
__device__ __forceinline__ uint32_t pack4(float a, float b, float c, float d, float inv) {
    int b0 = __float2int_rn(a * inv) & 255;
    int b1 = __float2int_rn(b * inv) & 255;
    int b2 = __float2int_rn(c * inv) & 255;
    int b3 = __float2int_rn(d * inv) & 255;
    return (uint32_t)(b0 | (b1 << 8) | (b2 << 16) | (b3 << 24));
}

// ---------------------------------------------------------------
__global__ void zero_kernel() {
    int total = 3 * KC + KC * DIM + KC * NCLS;   // wsq, counts, wmaxb, esum, bhist
    for (int i = blockIdx.x * blockDim.x + threadIdx.x; i < total;
         i += gridDim.x * blockDim.x) {
        if (i < KC) g_wsq[i] = 0.0f;
        else if (i < 2 * KC) g_counts[i - KC] = 0.0f;
        else if (i < 3 * KC) g_wmaxb[i - 2 * KC] = 0;
        else if (i < 3 * KC + KC * DIM) g_esum[i - 3 * KC] = 0.0f;
        else g_bhist[i - 3 * KC - KC * DIM] = 0.0f;
    }
}

// Transpose W [D][K] -> W^T fp32 [K][D] + fused wsq + per-col |max|
__global__ void wt_kernel(const float* __restrict__ W) {
    __shared__ float tile[32][33];
    __shared__ float wsqp[8][32];
    __shared__ float wmxp[8][32];
    int k0 = blockIdx.x * 32, d0 = blockIdx.y * 32;
    int tx = threadIdx.x, ty = threadIdx.y;   // (32, 8)
    float sq = 0.0f, mx = 0.0f;
    #pragma unroll
    for (int j = 0; j < 4; j++) {
        size_t gi = (size_t)(d0 + ty + 8 * j) * KC + k0 + tx;
        float v = W[gi];
        tile[ty + 8 * j][tx] = v;
        sq += v * v;
        mx = fmaxf(mx, fabsf(v));
    }
    wsqp[ty][tx] = sq;
    wmxp[ty][tx] = mx;
    __syncthreads();
    if (ty == 0) {
        float s = 0.0f, m = 0.0f;
        #pragma unroll
        for (int r = 0; r < 8; r++) { s += wsqp[r][tx]; m = fmaxf(m, wmxp[r][tx]); }
        atomicAdd(&g_wsq[k0 + tx], s);
        atomicMax(&g_wmaxb[k0 + tx], __float_as_int(m));
    }
    #pragma unroll
    for (int j = 0; j < 4; j++)
        g_wt32[(size_t)(k0 + ty + 8 * j) * DIM + d0 + tx] = tile[tx][ty + 8 * j];
}

// Quantize W^T -> int8 with per-column scale
__global__ void wq_kernel() {
    int idx = blockIdx.x * 256 + threadIdx.x;   // one per 4 elements
    if (idx >= KC * DIM / 4) return;
    int k = idx >> 7;                 // DIM/4 = 128
    int d4 = (idx & 127) * 4;
    float m = __int_as_float(g_wmaxb[k]);
    float inv = 127.0f / fmaxf(m, 1e-30f);
    const float4 v = *reinterpret_cast<const float4*>(&g_wt32[(size_t)k * DIM + d4]);
    *reinterpret_cast<uint32_t*>(&g_wq8t[(size_t)k * DIM + d4]) =
        pack4(v.x, v.y, v.z, v.w, inv);
    if ((idx & 127) == 0) g_wsc[k] = m / 127.0f;
}

// ---------------------------------------------------------------
// int8 mma.sync GEMM + fused quant/argmin/rescue/scatter.
// 64 rows/CTA, 1024 CTAs, 2 CTAs per SM (phase overlap).
// 8 warps (2m x 4n), warp tile 32x32.  B chunks 128n x 64d, 80B rows,
// 2-stage cp.async ring.
// ---------------------------------------------------------------
#define SA_OFF   0                     // 32768: A [64][512B], swizzled
#define SB_OFF   32768                 // 2 x 10240 B ring, 80B rows
#define WSQ_OFF  (SB_OFF + 20480)      // 53248
#define SWC_OFF  (WSQ_OFF + 4096)      // 57344
#define XSC_OFF  (SWC_OFF + 4096)      // 61440
#define AMK_OFF  (XSC_OFF + 256)       // 61696
#define CAND_OFF (AMK_OFF + 256)       // 61952
#define RED_OFF  SB_OFF                // reuse ring for merge (64*16*16=16KB)
#define SM_TOTAL (CAND_OFF + 1024)     // 62976  (x2 CTAs = 125952)
#define RESCUE_T 6.0f

__device__ __forceinline__ void load_b_chunk(uint32_t smb, int c, int tid) {
    int stage = c & 1;
    int d0 = (c & 7) * 64, n0 = (c >> 3) * 128;
    #pragma unroll
    for (int t = 0; t < 2; t++) {
        int ul = t * 256 + tid;          // 512 16B units (8KB data)
        int n = ul >> 2, u = ul & 3;     // 128 rows x 4 units (64B)
        cp_async16(smb + SB_OFF + stage * 10240 + n * 80 + u * 16,
                   &g_wq8t[(size_t)(n0 + n) * DIM + d0 + u * 16]);
    }
}

__global__ __launch_bounds__(256, 2)
void argmin_mma(const float* __restrict__ X, const int* __restrict__ keys,
                float* __restrict__ out_am) {
    extern __shared__ unsigned char sm[];
    uint32_t smb = smem_u32(sm);
    float*  s_wsq  = (float*)(sm + WSQ_OFF);
    float*  s_swc  = (float*)(sm + SWC_OFF);
    float*  s_xsc  = (float*)(sm + XSC_OFF);
    int*    s_amk  = (int*)(sm + AMK_OFF);
    int*    s_cand = (int*)(sm + CAND_OFF);    // [64][4]
    float4* red    = (float4*)(sm + RED_OFF);

    int tid  = threadIdx.x;
    int lane = tid & 31;
    int wid  = tid >> 5;
    int wm   = wid >> 2;        // 0..1 -> rows wm*32..+32
    int wn   = wid & 3;         // 0..3 -> cols wn*32..+32
    int row0 = blockIdx.x * 64;

    // start B pipeline first so quant overlaps the loads
    load_b_chunk(smb, 0, tid);
    CP_COMMIT();

    #pragma unroll
    for (int i = tid; i < KC; i += 256) { s_wsq[i] = g_wsq[i]; s_swc[i] = g_wsc[i]; }

    // ---- FUSED X quantization: warp per row, 8 rows per warp ----
    #pragma unroll
    for (int i = 0; i < 8; i++) {
        int r = wid * 8 + i;
        const float4* xp = reinterpret_cast<const float4*>(
            &X[(size_t)(row0 + r) * DIM + lane * 16]);
        float4 v0 = xp[0], v1 = xp[1], v2 = xp[2], v3 = xp[3];
        float mx8 = fmaxf(fmaxf(fmaxf(fabsf(v0.x), fabsf(v0.y)),
                                fmaxf(fabsf(v0.z), fabsf(v0.w))),
                          fmaxf(fmaxf(fabsf(v1.x), fabsf(v1.y)),
                                fmaxf(fabsf(v1.z), fabsf(v1.w))));
        mx8 = fmaxf(mx8, fmaxf(fmaxf(fabsf(v2.x), fabsf(v2.y)),
                               fmaxf(fabsf(v2.z), fabsf(v2.w))));
        mx8 = fmaxf(mx8, fmaxf(fmaxf(fabsf(v3.x), fabsf(v3.y)),
                               fmaxf(fabsf(v3.z), fabsf(v3.w))));
        #pragma unroll
        for (int o = 16; o > 0; o >>= 1)
            mx8 = fmaxf(mx8, __shfl_xor_sync(0xffffffff, mx8, o));
        float m = fmaxf(mx8, 1e-30f);
        float inv = 127.0f / m;
        uint4 q;
        q.x = pack4(v0.x, v0.y, v0.z, v0.w, inv);
        q.y = pack4(v1.x, v1.y, v1.z, v1.w, inv);
        q.z = pack4(v2.x, v2.y, v2.z, v2.w, inv);
        q.w = pack4(v3.x, v3.y, v3.z, v3.w, inv);
        *reinterpret_cast<uint4*>(sm + SA_OFF + r * 512 + ((lane ^ (r & 7)) * 16)) = q;
        if (lane == 0) s_xsc[r] = m / 127.0f;
    }

    float tv1[4], tv2[4];
    int   tk1[4], tk2[4];
    #pragma unroll
    for (int s = 0; s < 4; s++) { tv1[s] = FLT_MAX; tv2[s] = FLT_MAX; tk1[s] = KC; tk2[s] = KC; }

    int kl = lane & 15;
    int hi = lane >> 4;
    int mx = lane & 7;

    for (int nc = 0; nc < 8; nc++) {
        int acc[2][4][4];
        #pragma unroll
        for (int i = 0; i < 2; i++)
            #pragma unroll
            for (int j = 0; j < 4; j++)
                #pragma unroll
                for (int c = 0; c < 4; c++) acc[i][j][c] = 0;

        for (int dc = 0; dc < 8; dc++) {
            int c = nc * 8 + dc;
            if (c + 1 < 64) load_b_chunk(smb, c + 1, tid);
            CP_COMMIT();
            CP_WAIT1();                   // chunk c complete
            __syncthreads();              // B visible + A quant visible (1st iter)
            uint32_t bbase = smb + SB_OFF + (c & 1) * 10240;
            #pragma unroll
            for (int ks = 0; ks < 2; ks++) {
                uint32_t a[2][4];
                #pragma unroll
                for (int i = 0; i < 2; i++) {
                    int row = wm * 32 + i * 16 + kl;
                    int u = dc * 4 + ks * 2 + hi;   // 16B unit within 512B row
                    ldsm_x4(a[i], smb + SA_OFF + row * 512 + ((u ^ mx) * 16));
                }
                uint32_t bfr[2][4];
                #pragma unroll
                for (int nt = 0; nt < 2; nt++)
                    ldsm_x4(bfr[nt], bbase + (wn * 32 + nt * 16 + kl) * 80 +
                                     ks * 32 + hi * 16);
                #pragma unroll
                for (int i = 0; i < 2; i++)
                    #pragma unroll
                    for (int jj = 0; jj < 4; jj++) {
                        int g = jj >> 1, o = jj & 1;
                        mma_s8(acc[i][jj], a[i], bfr[g][0 + o], bfr[g][2 + o]);
                    }
            }
            __syncthreads();              // compute done before stage reuse
        }

        // ---- epilogue: dequant scores + running top-2 per row-slot ----
        int kbase = nc * 128 + wn * 32 + (lane & 3) * 2;
        #pragma unroll
        for (int i = 0; i < 2; i++)
            #pragma unroll
            for (int h = 0; h < 2; h++) {
                int slot = i * 2 + h;
                float sxr = s_xsc[wm * 32 + i * 16 + h * 8 + (lane >> 2)];
                float m2sx = -2.0f * sxr;
                #pragma unroll
                for (int j = 0; j < 4; j++) {
                    int kg = kbase + j * 8;
                    float s0 = fmaf((float)acc[i][j][h * 2]     * s_swc[kg],     m2sx, s_wsq[kg]);
                    float s1 = fmaf((float)acc[i][j][h * 2 + 1] * s_swc[kg + 1], m2sx, s_wsq[kg + 1]);
                    if (s0 < tv1[slot])      { tv2[slot] = tv1[slot]; tk2[slot] = tk1[slot]; tv1[slot] = s0; tk1[slot] = kg; }
                    else if (s0 < tv2[slot]) { tv2[slot] = s0; tk2[slot] = kg; }
                    if (s1 < tv1[slot])      { tv2[slot] = tv1[slot]; tk2[slot] = tk1[slot]; tv1[slot] = s1; tk1[slot] = kg + 1; }
                    else if (s1 < tv2[slot]) { tv2[slot] = s1; tk2[slot] = kg + 1; }
                }
            }
    }

    // ---- per-thread top-2 -> merge smem (ring no longer needed) ----
    __syncthreads();
    int ci = wn * 4 + (lane & 3);
    #pragma unroll
    for (int slot = 0; slot < 4; slot++) {
        int i = slot >> 1, h = slot & 1;
        int r = wm * 32 + i * 16 + h * 8 + (lane >> 2);
        float4 e;
        e.x = tv1[slot]; e.y = __int_as_float(tk1[slot]);
        e.z = tv2[slot]; e.w = __int_as_float(tk2[slot]);
        red[r * 16 + ci] = e;
    }
    __syncthreads();

    // ---- per-row merge: top-4 of 32 candidates, lexicographic (v, k) ----
    if (tid < 64) {
        float bv[4] = {FLT_MAX, FLT_MAX, FLT_MAX, FLT_MAX};
        int   bk[4] = {KC, KC, KC, KC};
        #pragma unroll
        for (int c = 0; c < 16; c++) {
            float4 e = red[tid * 16 + c];
            float cv[2] = {e.x, e.z};
            int   ck[2] = {__float_as_int(e.y), __float_as_int(e.w)};
            #pragma unroll
            for (int w = 0; w < 2; w++) {
                float v = cv[w]; int k = ck[w];
                if (v < bv[3] || (v == bv[3] && k < bk[3])) {
                    bv[3] = v; bk[3] = k;
                    if (bv[3] < bv[2] || (bv[3] == bv[2] && bk[3] < bk[2])) {
                        float t = bv[2]; bv[2] = bv[3]; bv[3] = t;
                        int ti = bk[2]; bk[2] = bk[3]; bk[3] = ti;
                    }
                    if (bv[2] < bv[1] || (bv[2] == bv[1] && bk[2] < bk[1])) {
                        float t = bv[1]; bv[1] = bv[2]; bv[2] = t;
                        int ti = bk[1]; bk[1] = bk[2]; bk[2] = ti;
                    }
                    if (bv[1] < bv[0] || (bv[1] == bv[0] && bk[1] < bk[0])) {
                        float t = bv[0]; bv[0] = bv[1]; bv[1] = t;
                        int ti = bk[0]; bk[0] = bk[1]; bk[1] = ti;
                    }
                }
            }
        }
        int b = row0 + tid;
        if (bv[1] - bv[0] > RESCUE_T) {
            g_argmin[b] = bk[0];
            out_am[b] = (float)bk[0];
            s_amk[tid] = bk[0];
        } else {
            s_amk[tid] = -1;
            #pragma unroll
            for (int w = 0; w < 4; w++) s_cand[tid * 4 + w] = bk[w];
        }
    }
    __syncthreads();

    // ---- FUSED rescue + scatter (warp per row) ----
    for (int rr = wid; rr < 64; rr += 8) {
        int k = s_amk[rr];
        int b = row0 + rr;
        const float* xr = X + (size_t)b * DIM;
        if (k < 0) {
            int kk[4];
            #pragma unroll
            for (int w = 0; w < 4; w++) kk[w] = s_cand[rr * 4 + w];
            float dot[4] = {0.0f, 0.0f, 0.0f, 0.0f};
            #pragma unroll 4
            for (int d = lane; d < DIM; d += 32) {
                float x = xr[d];
                #pragma unroll
                for (int w = 0; w < 4; w++)
                    dot[w] += x * g_wt32[(size_t)kk[w] * DIM + d];
            }
            #pragma unroll
            for (int off = 16; off > 0; off >>= 1)
                #pragma unroll
                for (int w = 0; w < 4; w++)
                    dot[w] += __shfl_xor_sync(0xffffffff, dot[w], off);
            int bi = KC;
            if (lane == 0) {
                float bvv = FLT_MAX;
                #pragma unroll
                for (int w = 0; w < 4; w++) {
                    float s = s_wsq[kk[w]] - 2.0f * dot[w];
                    if (s < bvv || (s == bvv && kk[w] < bi)) { bvv = s; bi = kk[w]; }
                }
                g_argmin[b] = bi;
                out_am[b] = (float)bi;
            }
            k = __shfl_sync(0xffffffff, bi, 0);
        }
        if (lane == 0) {
            atomicAdd(&g_counts[k], 1.0f);
            atomicAdd(&g_bhist[k * NCLS + keys[b]], 1.0f);
        }
        float* es = g_esum + (size_t)k * DIM;
        #pragma unroll
        for (int i = 0; i < 4; i++) {
            int d = (lane + i * 32) * 4;
            red_v4(es + d, *reinterpret_cast<const float4*>(xr + d));
        }
    }
}

// ---------------------------------------------------------------
__global__ void fincs_kernel(const float* __restrict__ cs,
                             float* __restrict__ out_cs) {
    __shared__ float sred[KC];
    int k = threadIdx.x;
    float c = g_counts[k];
    if (c == 0.0f) c = 1.0f;
    float ncs = cs[k] * GAMMA + (1.0f - GAMMA) * c;
    out_cs[k] = ncs;
    sred[k] = ncs;
    __syncthreads();
    for (int s = KC / 2; s > 0; s >>= 1) {
        if (k < s) sred[k] += sred[k + s];
        __syncthreads();
    }
    if (k == 0) g_n = sred[0];
}

__global__ void finw_kernel(const float* __restrict__ ea,
                            const float* __restrict__ out_cs,
                            float* __restrict__ out_w,
                            float* __restrict__ out_ea) {
    __shared__ float tile[32][33];
    int k0 = blockIdx.x * 32, d0 = blockIdx.y * 32;
    int tx = threadIdx.x, ty = threadIdx.y;   // (32, 8)
    #pragma unroll
    for (int j = 0; j < 4; j++)
        tile[ty + 8 * j][tx] = g_esum[(size_t)(k0 + ty + 8 * j) * DIM + d0 + tx];
    __syncthreads();
    float n = g_n;
    float csn = (out_cs[k0 + tx] + EPSV) / (n + KC * EPSV) * n;
    #pragma unroll
    for (int j = 0; j < 4; j++) {
        size_t i = (size_t)(d0 + ty + 8 * j) * KC + k0 + tx;
        float e = ea[i] * GAMMA + (1.0f - GAMMA) * tile[tx][ty + 8 * j];
        out_ea[i] = e;
        out_w[i] = e / csn;
    }
}

__global__ void finh_kernel(const float* __restrict__ hist,
                            float* __restrict__ out_h) {
    int i = blockIdx.x * blockDim.x + threadIdx.x;
    if (i >= KCC) return;
    out_h[i] = hist[i] * GAMMA + (1.0f - GAMMA) * g_bhist[i];
}

// ---------------------------------------------------------------
extern "C" void kernel_launch(void* const* d_in, const int* in_sizes, int n_in,
                              void* d_out, int out_size) {
    const float* X    = (const float*)d_in[0];  // [B,D]
    const int*   keys = (const int*)  d_in[1];  // [B]
    const float* W    = (const float*)d_in[2];  // [D,K]
    const float* cs   = (const float*)d_in[3];  // [K]
    const float* ea   = (const float*)d_in[4];  // [D,K]
    const float* hist = (const float*)d_in[5];  // [K,C]

    float* out    = (float*)d_out;
    float* out_w  = out;                        // D*K
    float* out_cs = out + DK;                   // K
    float* out_ea = out + DK + KC;              // D*K
    float* out_h  = out + DK + KC + DK;         // K*C
    float* out_am = out + DK + KC + DK + KCC;   // B

    cudaFuncSetAttribute(argmin_mma, cudaFuncAttributeMaxDynamicSharedMemorySize,
                         SM_TOTAL);

    zero_kernel<<<148, 256>>>();
    wt_kernel<<<dim3(KC / 32, DIM / 32), dim3(32, 8)>>>(W);
    wq_kernel<<<(KC * DIM / 4 + 255) / 256, 256>>>();
    argmin_mma<<<BATCH / 64, 256, SM_TOTAL>>>(X, keys, out_am);
    fincs_kernel<<<1, KC>>>(cs, out_cs);
    finw_kernel<<<dim3(KC / 32, DIM / 32), dim3(32, 8)>>>(ea, out_cs, out_w, out_ea);
    finh_kernel<<<(KCC + 255) / 256, 256>>>(hist, out_h);
}

// round 15
// speedup vs baseline: 2.2036x; 1.0171x over previous
#include <cuda_runtime.h>
#include <cuda_bf16.h>
#include <cstdint>
#include <float.h>

#define BATCH 65536
#define DIM   512
#define KC    1024
#define NCLS  100
#define GAMMA 0.99f
#define EPSV  1e-5f

#define DK (DIM * KC)      // 524288
#define KCC (KC * NCLS)    // 102400

// ---------------- scratch (device globals) ----------------
__device__ float                 g_wsq[KC];
__device__ float                 g_counts[KC];
__device__ __align__(16) float   g_esum[KC * DIM];     // [K][D]
__device__ float                 g_bhist[KC * NCLS];
__device__ int                   g_argmin[BATCH];
__device__ float                 g_n;
__device__ float                 g_wt32[KC * DIM];     // W^T fp32 [K][D] (rescue)
__device__ int                   g_wmaxb[KC];          // per-col |W| max (float bits)
__device__ float                 g_wsc[KC];            // per-col W scale
__device__ __align__(16) int8_t  g_wq8t[KC * DIM];     // int8 W^T [K][D]

// ---------------- PTX helpers (sm_100-base safe) ----------------
__device__ __forceinline__ uint32_t smem_u32(const void* p) {
    uint32_t a;
    asm("{ .reg .u64 t; cvta.to.shared.u64 t, %1; cvt.u32.u64 %0, t; }"
        : "=r"(a) : "l"(p));
    return a;
}
__device__ __forceinline__ void ldsm_x4(uint32_t* r, uint32_t addr) {
    asm volatile("ldmatrix.sync.aligned.m8n8.x4.shared.b16 {%0,%1,%2,%3}, [%4];"
                 : "=r"(r[0]), "=r"(r[1]), "=r"(r[2]), "=r"(r[3]) : "r"(addr));
}
__device__ __forceinline__ void mma_s8(int* c, const uint32_t* a,
                                       uint32_t b0, uint32_t b1) {
    asm volatile("mma.sync.aligned.m16n8k32.row.col.s32.s8.s8.s32 "
                 "{%0,%1,%2,%3}, {%4,%5,%6,%7}, {%8,%9}, {%0,%1,%2,%3};"
                 : "+r"(c[0]), "+r"(c[1]), "+r"(c[2]), "+r"(c[3])
                 : "r"(a[0]), "r"(a[1]), "r"(a[2]), "r"(a[3]), "r"(b0), "r"(b1));
}
__device__ __forceinline__ void cp_async16(uint32_t dst, const void* src) {
    asm volatile("cp.async.cg.shared.global [%0], [%1], 16;"
                 :: "r"(dst), "l"(src) : "memory");
}
#define CP_COMMIT() asm volatile("cp.async.commit_group;" ::: "memory")
#define CP_WAIT2()  asm volatile("cp.async.wait_group 2;"  ::: "memory")
__device__ __forceinline__ void red_v4(float* addr, float4 v) {
    asm volatile("red.global.add.v4.f32 [%0], {%1, %2, %3, %4};"
                 :: "l"(addr), "f"(v.x), "f"(v.y), "f"(v.z), "f"(v.w) : "memory");
}
__device__ __forceinline__ uint32_t pack4(float a, float b, float c, float d, float inv) {
    int b0 = __float2int_rn(a * inv) & 255;
    int b1 = __float2int_rn(b * inv) & 255;
    int b2 = __float2int_rn(c * inv) & 255;
    int b3 = __float2int_rn(d * inv) & 255;
    return (uint32_t)(b0 | (b1 << 8) | (b2 << 16) | (b3 << 24));
}

// ---------------------------------------------------------------
__global__ void zero_kernel() {
    int total = 3 * KC + KC * DIM + KC * NCLS;   // wsq, counts, wmaxb, esum, bhist
    for (int i = blockIdx.x * blockDim.x + threadIdx.x; i < total;
         i += gridDim.x * blockDim.x) {
        if (i < KC) g_wsq[i] = 0.0f;
        else if (i < 2 * KC) g_counts[i - KC] = 0.0f;
        else if (i < 3 * KC) g_wmaxb[i - 2 * KC] = 0;
        else if (i < 3 * KC + KC * DIM) g_esum[i - 3 * KC] = 0.0f;
        else g_bhist[i - 3 * KC - KC * DIM] = 0.0f;
    }
}

// Transpose W [D][K] -> W^T fp32 [K][D] + fused wsq + per-col |max|
__global__ void wt_kernel(const float* __restrict__ W) {
    __shared__ float tile[32][33];
    __shared__ float wsqp[8][32];
    __shared__ float wmxp[8][32];
    int k0 = blockIdx.x * 32, d0 = blockIdx.y * 32;
    int tx = threadIdx.x, ty = threadIdx.y;   // (32, 8)
    float sq = 0.0f, mx = 0.0f;
    #pragma unroll
    for (int j = 0; j < 4; j++) {
        size_t gi = (size_t)(d0 + ty + 8 * j) * KC + k0 + tx;
        float v = W[gi];
        tile[ty + 8 * j][tx] = v;
        sq += v * v;
        mx = fmaxf(mx, fabsf(v));
    }
    wsqp[ty][tx] = sq;
    wmxp[ty][tx] = mx;
    __syncthreads();
    if (ty == 0) {
        float s = 0.0f, m = 0.0f;
        #pragma unroll
        for (int r = 0; r < 8; r++) { s += wsqp[r][tx]; m = fmaxf(m, wmxp[r][tx]); }
        atomicAdd(&g_wsq[k0 + tx], s);
        atomicMax(&g_wmaxb[k0 + tx], __float_as_int(m));
    }
    #pragma unroll
    for (int j = 0; j < 4; j++)
        g_wt32[(size_t)(k0 + ty + 8 * j) * DIM + d0 + tx] = tile[tx][ty + 8 * j];
}

// Quantize W^T -> int8 with per-column scale
__global__ void wq_kernel() {
    int idx = blockIdx.x * 256 + threadIdx.x;   // one per 4 elements
    if (idx >= KC * DIM / 4) return;
    int k = idx >> 7;                 // DIM/4 = 128
    int d4 = (idx & 127) * 4;
    float m = __int_as_float(g_wmaxb[k]);
    float inv = 127.0f / fmaxf(m, 1e-30f);
    const float4 v = *reinterpret_cast<const float4*>(&g_wt32[(size_t)k * DIM + d4]);
    *reinterpret_cast<uint32_t*>(&g_wq8t[(size_t)k * DIM + d4]) =
        pack4(v.x, v.y, v.z, v.w, inv);
    if ((idx & 127) == 0) g_wsc[k] = m / 127.0f;
}

// ---------------------------------------------------------------
// int8 mma.sync GEMM + fused quant/argmin/rescue/scatter.
// 64 rows/CTA, 1024 CTAs, 2 CTAs per SM (phase overlap).
// 8 warps (2m x 4n), warp tile 32x32.  B chunks 128n x 64d, 80B rows,
// 4-stage cp.async ring, ONE __syncthreads per chunk.
// ---------------------------------------------------------------
#define SA_OFF   0                     // 32768: A [64][512B], swizzled
#define SB_OFF   32768                 // 4 x 10240 B ring, 80B rows
#define WSQ_OFF  (SB_OFF + 40960)      // 73728
#define SWC_OFF  (WSQ_OFF + 4096)      // 77824
#define XSC_OFF  (SWC_OFF + 4096)      // 81920
#define AMK_OFF  (XSC_OFF + 256)       // 82176
#define CAND_OFF (AMK_OFF + 256)       // 82432
#define RED_OFF  SB_OFF                // reuse ring for merge (64*16*16=16KB)
#define SM_TOTAL (CAND_OFF + 1024)     // 83456  (x2 CTAs = 166912)
#define RESCUE_T 6.0f

__device__ __forceinline__ void load_b_chunk(uint32_t smb, int c, int tid) {
    int stage = c & 3;
    int d0 = (c & 7) * 64, n0 = (c >> 3) * 128;
    #pragma unroll
    for (int t = 0; t < 2; t++) {
        int ul = t * 256 + tid;          // 512 16B units (8KB data)
        int n = ul >> 2, u = ul & 3;     // 128 rows x 4 units (64B)
        cp_async16(smb + SB_OFF + stage * 10240 + n * 80 + u * 16,
                   &g_wq8t[(size_t)(n0 + n) * DIM + d0 + u * 16]);
    }
}

__global__ __launch_bounds__(256, 2)
void argmin_mma(const float* __restrict__ X, const int* __restrict__ keys,
                float* __restrict__ out_am) {
    extern __shared__ unsigned char sm[];
    uint32_t smb = smem_u32(sm);
    float*  s_wsq  = (float*)(sm + WSQ_OFF);
    float*  s_swc  = (float*)(sm + SWC_OFF);
    float*  s_xsc  = (float*)(sm + XSC_OFF);
    int*    s_amk  = (int*)(sm + AMK_OFF);
    int*    s_cand = (int*)(sm + CAND_OFF);    // [64][4]
    float4* red    = (float4*)(sm + RED_OFF);

    int tid  = threadIdx.x;
    int lane = tid & 31;
    int wid  = tid >> 5;
    int wm   = wid >> 2;        // 0..1 -> rows wm*32..+32
    int wn   = wid & 3;         // 0..3 -> cols wn*32..+32
    int row0 = blockIdx.x * 64;

    // prologue: stages 0..2 in flight while we quantize A
    load_b_chunk(smb, 0, tid); CP_COMMIT();
    load_b_chunk(smb, 1, tid); CP_COMMIT();
    load_b_chunk(smb, 2, tid); CP_COMMIT();

    #pragma unroll
    for (int i = tid; i < KC; i += 256) { s_wsq[i] = g_wsq[i]; s_swc[i] = g_wsc[i]; }

    // ---- FUSED X quantization: warp per row, 8 rows per warp ----
    #pragma unroll
    for (int i = 0; i < 8; i++) {
        int r = wid * 8 + i;
        const float4* xp = reinterpret_cast<const float4*>(
            &X[(size_t)(row0 + r) * DIM + lane * 16]);
        float4 v0 = xp[0], v1 = xp[1], v2 = xp[2], v3 = xp[3];
        float mx8 = fmaxf(fmaxf(fmaxf(fabsf(v0.x), fabsf(v0.y)),
                                fmaxf(fabsf(v0.z), fabsf(v0.w))),
                          fmaxf(fmaxf(fabsf(v1.x), fabsf(v1.y)),
                                fmaxf(fabsf(v1.z), fabsf(v1.w))));
        mx8 = fmaxf(mx8, fmaxf(fmaxf(fabsf(v2.x), fabsf(v2.y)),
                               fmaxf(fabsf(v2.z), fabsf(v2.w))));
        mx8 = fmaxf(mx8, fmaxf(fmaxf(fabsf(v3.x), fabsf(v3.y)),
                               fmaxf(fabsf(v3.z), fabsf(v3.w))));
        #pragma unroll
        for (int o = 16; o > 0; o >>= 1)
            mx8 = fmaxf(mx8, __shfl_xor_sync(0xffffffff, mx8, o));
        float m = fmaxf(mx8, 1e-30f);
        float inv = 127.0f / m;
        uint4 q;
        q.x = pack4(v0.x, v0.y, v0.z, v0.w, inv);
        q.y = pack4(v1.x, v1.y, v1.z, v1.w, inv);
        q.z = pack4(v2.x, v2.y, v2.z, v2.w, inv);
        q.w = pack4(v3.x, v3.y, v3.z, v3.w, inv);
        *reinterpret_cast<uint4*>(sm + SA_OFF + r * 512 + ((lane ^ (r & 7)) * 16)) = q;
        if (lane == 0) s_xsc[r] = m / 127.0f;
    }

    float tv1[4], tv2[4];
    int   tk1[4], tk2[4];
    #pragma unroll
    for (int s = 0; s < 4; s++) { tv1[s] = FLT_MAX; tv2[s] = FLT_MAX; tk1[s] = KC; tk2[s] = KC; }

    int kl = lane & 15;
    int hi = lane >> 4;
    int mx = lane & 7;

    for (int nc = 0; nc < 8; nc++) {
        int acc[2][4][4];
        #pragma unroll
        for (int i = 0; i < 2; i++)
            #pragma unroll
            for (int j = 0; j < 4; j++)
                #pragma unroll
                for (int c = 0; c < 4; c++) acc[i][j][c] = 0;

        for (int dc = 0; dc < 8; dc++) {
            int c = nc * 8 + dc;
            CP_WAIT2();                   // chunk c landed (<=2 younger outstanding)
            __syncthreads();              // publish chunk c; stage (c+3)&3 free
            if (c + 3 < 64) load_b_chunk(smb, c + 3, tid);
            CP_COMMIT();                  // empty groups keep wait math exact
            uint32_t bbase = smb + SB_OFF + (c & 3) * 10240;
            #pragma unroll
            for (int ks = 0; ks < 2; ks++) {
                uint32_t a[2][4];
                #pragma unroll
                for (int i = 0; i < 2; i++) {
                    int row = wm * 32 + i * 16 + kl;
                    int u = dc * 4 + ks * 2 + hi;   // 16B unit within 512B row
                    ldsm_x4(a[i], smb + SA_OFF + row * 512 + ((u ^ mx) * 16));
                }
                uint32_t bfr[2][4];
                #pragma unroll
                for (int nt = 0; nt < 2; nt++)
                    ldsm_x4(bfr[nt], bbase + (wn * 32 + nt * 16 + kl) * 80 +
                                     ks * 32 + hi * 16);
                #pragma unroll
                for (int i = 0; i < 2; i++)
                    #pragma unroll
                    for (int jj = 0; jj < 4; jj++) {
                        int g = jj >> 1, o = jj & 1;
                        mma_s8(acc[i][jj], a[i], bfr[g][0 + o], bfr[g][2 + o]);
                    }
            }
        }

        // ---- epilogue: dequant scores + running top-2 per row-slot ----
        int kbase = nc * 128 + wn * 32 + (lane & 3) * 2;
        #pragma unroll
        for (int i = 0; i < 2; i++)
            #pragma unroll
            for (int h = 0; h < 2; h++) {
                int slot = i * 2 + h;
                float sxr = s_xsc[wm * 32 + i * 16 + h * 8 + (lane >> 2)];
                float m2sx = -2.0f * sxr;
                #pragma unroll
                for (int j = 0; j < 4; j++) {
                    int kg = kbase + j * 8;
                    float s0 = fmaf((float)acc[i][j][h * 2]     * s_swc[kg],     m2sx, s_wsq[kg]);
                    float s1 = fmaf((float)acc[i][j][h * 2 + 1] * s_swc[kg + 1], m2sx, s_wsq[kg + 1]);
                    if (s0 < tv1[slot])      { tv2[slot] = tv1[slot]; tk2[slot] = tk1[slot]; tv1[slot] = s0; tk1[slot] = kg; }
                    else if (s0 < tv2[slot]) { tv2[slot] = s0; tk2[slot] = kg; }
                    if (s1 < tv1[slot])      { tv2[slot] = tv1[slot]; tk2[slot] = tk1[slot]; tv1[slot] = s1; tk1[slot] = kg + 1; }
                    else if (s1 < tv2[slot]) { tv2[slot] = s1; tk2[slot] = kg + 1; }
                }
            }
    }

    // ---- per-thread top-2 -> merge smem (ring no longer needed) ----
    __syncthreads();
    int ci = wn * 4 + (lane & 3);
    #pragma unroll
    for (int slot = 0; slot < 4; slot++) {
        int i = slot >> 1, h = slot & 1;
        int r = wm * 32 + i * 16 + h * 8 + (lane >> 2);
        float4 e;
        e.x = tv1[slot]; e.y = __int_as_float(tk1[slot]);
        e.z = tv2[slot]; e.w = __int_as_float(tk2[slot]);
        red[r * 16 + ci] = e;
    }
    __syncthreads();

    // ---- per-row merge: top-4 of 32 candidates, lexicographic (v, k) ----
    if (tid < 64) {
        float bv[4] = {FLT_MAX, FLT_MAX, FLT_MAX, FLT_MAX};
        int   bk[4] = {KC, KC, KC, KC};
        #pragma unroll
        for (int c = 0; c < 16; c++) {
            float4 e = red[tid * 16 + c];
            float cv[2] = {e.x, e.z};
            int   ck[2] = {__float_as_int(e.y), __float_as_int(e.w)};
            #pragma unroll
            for (int w = 0; w < 2; w++) {
                float v = cv[w]; int k = ck[w];
                if (v < bv[3] || (v == bv[3] && k < bk[3])) {
                    bv[3] = v; bk[3] = k;
                    if (bv[3] < bv[2] || (bv[3] == bv[2] && bk[3] < bk[2])) {
                        float t = bv[2]; bv[2] = bv[3]; bv[3] = t;
                        int ti = bk[2]; bk[2] = bk[3]; bk[3] = ti;
                    }
                    if (bv[2] < bv[1] || (bv[2] == bv[1] && bk[2] < bk[1])) {
                        float t = bv[1]; bv[1] = bv[2]; bv[2] = t;
                        int ti = bk[1]; bk[1] = bk[2]; bk[2] = ti;
                    }
                    if (bv[1] < bv[0] || (bv[1] == bv[0] && bk[1] < bk[0])) {
                        float t = bv[0]; bv[0] = bv[1]; bv[1] = t;
                        int ti = bk[0]; bk[0] = bk[1]; bk[1] = ti;
                    }
                }
            }
        }
        int b = row0 + tid;
        if (bv[1] - bv[0] > RESCUE_T) {
            g_argmin[b] = bk[0];
            out_am[b] = (float)bk[0];
            s_amk[tid] = bk[0];
        } else {
            s_amk[tid] = -1;
            #pragma unroll
            for (int w = 0; w < 4; w++) s_cand[tid * 4 + w] = bk[w];
        }
    }
    __syncthreads();

    // ---- FUSED rescue + scatter (warp per row) ----
    for (int rr = wid; rr < 64; rr += 8) {
        int k = s_amk[rr];
        int b = row0 + rr;
        const float* xr = X + (size_t)b * DIM;
        if (k < 0) {
            int kk[4];
            #pragma unroll
            for (int w = 0; w < 4; w++) kk[w] = s_cand[rr * 4 + w];
            float dot[4] = {0.0f, 0.0f, 0.0f, 0.0f};
            #pragma unroll 4
            for (int d = lane; d < DIM; d += 32) {
                float x = xr[d];
                #pragma unroll
                for (int w = 0; w < 4; w++)
                    dot[w] += x * g_wt32[(size_t)kk[w] * DIM + d];
            }
            #pragma unroll
            for (int off = 16; off > 0; off >>= 1)
                #pragma unroll
                for (int w = 0; w < 4; w++)
                    dot[w] += __shfl_xor_sync(0xffffffff, dot[w], off);
            int bi = KC;
            if (lane == 0) {
                float bvv = FLT_MAX;
                #pragma unroll
                for (int w = 0; w < 4; w++) {
                    float s = s_wsq[kk[w]] - 2.0f * dot[w];
                    if (s < bvv || (s == bvv && kk[w] < bi)) { bvv = s; bi = kk[w]; }
                }
                g_argmin[b] = bi;
                out_am[b] = (float)bi;
            }
            k = __shfl_sync(0xffffffff, bi, 0);
        }
        if (lane == 0) {
            atomicAdd(&g_counts[k], 1.0f);
            atomicAdd(&g_bhist[k * NCLS + keys[b]], 1.0f);
        }
        float* es = g_esum + (size_t)k * DIM;
        #pragma unroll
        for (int i = 0; i < 4; i++) {
            int d = (lane + i * 32) * 4;
            red_v4(es + d, *reinterpret_cast<const float4*>(xr + d));
        }
    }
}

// ---------------------------------------------------------------
__global__ void fincs_kernel(const float* __restrict__ cs,
                             float* __restrict__ out_cs) {
    __shared__ float sred[KC];
    int k = threadIdx.x;
    float c = g_counts[k];
    if (c == 0.0f) c = 1.0f;
    float ncs = cs[k] * GAMMA + (1.0f - GAMMA) * c;
    out_cs[k] = ncs;
    sred[k] = ncs;
    __syncthreads();
    for (int s = KC / 2; s > 0; s >>= 1) {
        if (k < s) sred[k] += sred[k + s];
        __syncthreads();
    }
    if (k == 0) g_n = sred[0];
}

__global__ void finw_kernel(const float* __restrict__ ea,
                            const float* __restrict__ out_cs,
                            float* __restrict__ out_w,
                            float* __restrict__ out_ea) {
    __shared__ float tile[32][33];
    int k0 = blockIdx.x * 32, d0 = blockIdx.y * 32;
    int tx = threadIdx.x, ty = threadIdx.y;   // (32, 8)
    #pragma unroll
    for (int j = 0; j < 4; j++)
        tile[ty + 8 * j][tx] = g_esum[(size_t)(k0 + ty + 8 * j) * DIM + d0 + tx];
    __syncthreads();
    float n = g_n;
    float csn = (out_cs[k0 + tx] + EPSV) / (n + KC * EPSV) * n;
    #pragma unroll
    for (int j = 0; j < 4; j++) {
        size_t i = (size_t)(d0 + ty + 8 * j) * KC + k0 + tx;
        float e = ea[i] * GAMMA + (1.0f - GAMMA) * tile[tx][ty + 8 * j];
        out_ea[i] = e;
        out_w[i] = e / csn;
    }
}

__global__ void finh_kernel(const float* __restrict__ hist,
                            float* __restrict__ out_h) {
    int i = blockIdx.x * blockDim.x + threadIdx.x;
    if (i >= KCC) return;
    out_h[i] = hist[i] * GAMMA + (1.0f - GAMMA) * g_bhist[i];
}

// ---------------------------------------------------------------
extern "C" void kernel_launch(void* const* d_in, const int* in_sizes, int n_in,
                              void* d_out, int out_size) {
    const float* X    = (const float*)d_in[0];  // [B,D]
    const int*   keys = (const int*)  d_in[1];  // [B]
    const float* W    = (const float*)d_in[2];  // [D,K]
    const float* cs   = (const float*)d_in[3];  // [K]
    const float* ea   = (const float*)d_in[4];  // [D,K]
    const float* hist = (const float*)d_in[5];  // [K,C]

    float* out    = (float*)d_out;
    float* out_w  = out;                        // D*K
    float* out_cs = out + DK;                   // K
    float* out_ea = out + DK + KC;              // D*K
    float* out_h  = out + DK + KC + DK;         // K*C
    float* out_am = out + DK + KC + DK + KCC;   // B

    cudaFuncSetAttribute(argmin_mma, cudaFuncAttributeMaxDynamicSharedMemorySize,
                         SM_TOTAL);

    zero_kernel<<<148, 256>>>();
    wt_kernel<<<dim3(KC / 32, DIM / 32), dim3(32, 8)>>>(W);
    wq_kernel<<<(KC * DIM / 4 + 255) / 256, 256>>>();
    argmin_mma<<<BATCH / 64, 256, SM_TOTAL>>>(X, keys, out_am);
    fincs_kernel<<<1, KC>>>(cs, out_cs);
    finw_kernel<<<dim3(KC / 32, DIM / 32), dim3(32, 8)>>>(ea, out_cs, out_w, out_ea);
    finh_kernel<<<(KCC + 255) / 256, 256>>>(hist, out_h);
}